// round 1
// baseline (speedup 1.0000x reference)
#include <cuda_runtime.h>

// Problem constants
#define Bb   2
#define Tt   2048
#define Dd   1024
#define Hh   16
#define HDIM 64
#define MTOT (Bb*Tt)        // 4096 rows

// Scratch (allocation-free rule: __device__ globals)
__device__ float g_q[Bb*Hh*Tt*HDIM];
__device__ float g_k[Bb*Hh*Tt*HDIM];
__device__ float g_v[Bb*Hh*Tt*HDIM];
__device__ float g_ctx[Bb*Tt*Dd];

// ---------------------------------------------------------------------------
// GEMM: C = A[M,1024] * W[1024,1024] (+bias).  64x64 block tile, BK=16,
// 256 threads, 4x4 micro-tile per thread, float4 smem reads.
// mode 0: write C row-major [M,1024] with bias (output projection)
// mode 1: write head-split layout [B,H,T,64]  (BN == head_dim, so
//         blockIdx.x IS the head index)
// ---------------------------------------------------------------------------
__global__ void gemm64(const float* __restrict__ A, const float* __restrict__ W,
                       float* __restrict__ C, const float* __restrict__ bias,
                       int mode)
{
    __shared__ float As[16][68];   // [k][m], pad 4 -> 16B-aligned float4 rows
    __shared__ float Ws[16][64];   // [k][n]

    const int tid = threadIdx.x;
    const int tx = tid & 15;       // n direction
    const int ty = tid >> 4;       // m direction
    const int m0 = blockIdx.y * 64;
    const int n0 = blockIdx.x * 64;

    float acc[4][4] = {};

    const float* Ap = A + (size_t)m0 * 1024;
    const float* Wp = W + n0;

    for (int k0 = 0; k0 < 1024; k0 += 16) {
        #pragma unroll
        for (int i = 0; i < 4; i++) {
            int idx = tid + i * 256;           // 64x16 A tile
            int m = idx >> 4, kk = idx & 15;
            As[kk][m] = Ap[(size_t)m * 1024 + k0 + kk];
        }
        #pragma unroll
        for (int i = 0; i < 4; i++) {
            int idx = tid + i * 256;           // 16x64 W tile
            int kk = idx >> 6, n = idx & 63;
            Ws[kk][n] = Wp[(size_t)(k0 + kk) * 1024 + n];
        }
        __syncthreads();

        #pragma unroll
        for (int kk = 0; kk < 16; kk++) {
            float4 a4 = *(const float4*)&As[kk][4 * ty];
            float4 b4 = *(const float4*)&Ws[kk][4 * tx];
            float a[4] = {a4.x, a4.y, a4.z, a4.w};
            float b[4] = {b4.x, b4.y, b4.z, b4.w};
            #pragma unroll
            for (int i = 0; i < 4; i++)
                #pragma unroll
                for (int j = 0; j < 4; j++)
                    acc[i][j] = fmaf(a[i], b[j], acc[i][j]);
        }
        __syncthreads();
    }

    if (mode == 0) {
        float4 bz = *(const float4*)&bias[n0 + 4 * tx];
        #pragma unroll
        for (int i = 0; i < 4; i++) {
            int m = m0 + 4 * ty + i;
            float4 o = make_float4(acc[i][0] + bz.x, acc[i][1] + bz.y,
                                   acc[i][2] + bz.z, acc[i][3] + bz.w);
            *(float4*)&C[(size_t)m * 1024 + n0 + 4 * tx] = o;
        }
    } else {
        int h = blockIdx.x;                    // BN == HDIM
        #pragma unroll
        for (int i = 0; i < 4; i++) {
            int m = m0 + 4 * ty + i;
            int b = m >> 11;                   // /T (2048)
            int t = m & 2047;
            float4 o = make_float4(acc[i][0], acc[i][1], acc[i][2], acc[i][3]);
            *(float4*)&C[(size_t)b * (Hh*Tt*HDIM) + (size_t)h * (Tt*HDIM)
                         + (size_t)t * HDIM + 4 * tx] = o;
        }
    }
}

// ---------------------------------------------------------------------------
// Causal flash attention: one block = 64 queries of one (b,h).
// 256 threads, 4q x 4d micro-tiles, online softmax, smem:
//   Qt [64][68]  (d-major, scaled by 1/sqrt(HD))  17408B
//   KP [64][68]  Kt (d-major) in phase 1, reused as P[q][c] in phase 2  17408B
//   Vs [64][64]  (c-major)  16384B          total 51200B dynamic
// ---------------------------------------------------------------------------
__global__ void flash64(const float* __restrict__ q, const float* __restrict__ k,
                        const float* __restrict__ v, float* __restrict__ ctx)
{
    extern __shared__ float sm[];
    float* Qt = sm;               // [64][68]
    float* KP = sm + 64 * 68;     // [64][68]
    float* Vs = KP + 64 * 68;     // [64][64]

    const int tid = threadIdx.x;
    const int tx = tid & 15;      // k-col / d-col direction
    const int ty = tid >> 4;      // q-row direction
    const int qt = blockIdx.x, h = blockIdx.y, b = blockIdx.z;
    const int q0 = qt * 64;

    const size_t bh = (size_t)(b * Hh + h) * (Tt * HDIM);
    const float* qb = q + bh;
    const float* kb = k + bh;
    const float* vb = v + bh;

    // Q tile, transposed + pre-scaled
    #pragma unroll
    for (int i = 0; i < 16; i++) {
        int idx = tid + i * 256;
        int r = idx >> 6, d = idx & 63;
        Qt[d * 68 + r] = qb[(size_t)(q0 + r) * HDIM + d] * 0.125f;
    }

    float mr[4], lr[4], O[4][4];
    #pragma unroll
    for (int i = 0; i < 4; i++) {
        mr[i] = -1e30f; lr[i] = 0.f;
        #pragma unroll
        for (int j = 0; j < 4; j++) O[i][j] = 0.f;
    }

    for (int kt = 0; kt <= qt; kt++) {
        const int k0 = kt * 64;
        __syncthreads();   // prior phase-2 readers done with KP/Vs
        #pragma unroll
        for (int i = 0; i < 16; i++) {
            int idx = tid + i * 256;
            int c = idx >> 6, d = idx & 63;
            float kvrow = kb[(size_t)(k0 + c) * HDIM + d];
            KP[d * 68 + c] = kvrow;                       // K transposed
            Vs[c * 64 + d] = vb[(size_t)(k0 + c) * HDIM + d];
        }
        __syncthreads();

        // Phase 1: S = Q K^T (scaled)
        float S[4][4] = {};
        #pragma unroll 16
        for (int d = 0; d < 64; d++) {
            float4 a4 = *(const float4*)&Qt[d * 68 + 4 * ty];
            float4 b4 = *(const float4*)&KP[d * 68 + 4 * tx];
            float a[4] = {a4.x, a4.y, a4.z, a4.w};
            float bb[4] = {b4.x, b4.y, b4.z, b4.w};
            #pragma unroll
            for (int i = 0; i < 4; i++)
                #pragma unroll
                for (int j = 0; j < 4; j++)
                    S[i][j] = fmaf(a[i], bb[j], S[i][j]);
        }

        if (kt == qt) {   // causal mask on diagonal tile
            #pragma unroll
            for (int i = 0; i < 4; i++)
                #pragma unroll
                for (int j = 0; j < 4; j++)
                    if (k0 + 4 * tx + j > q0 + 4 * ty + i) S[i][j] = -1e30f;
        }

        // Online softmax update
        float P[4][4];
        #pragma unroll
        for (int i = 0; i < 4; i++) {
            float mx = fmaxf(fmaxf(S[i][0], S[i][1]), fmaxf(S[i][2], S[i][3]));
            #pragma unroll
            for (int o = 8; o; o >>= 1)
                mx = fmaxf(mx, __shfl_xor_sync(0xffffffffu, mx, o, 16));
            float nm = fmaxf(mr[i], mx);
            float s = 0.f;
            #pragma unroll
            for (int j = 0; j < 4; j++) {
                P[i][j] = __expf(S[i][j] - nm);
                s += P[i][j];
            }
            #pragma unroll
            for (int o = 8; o; o >>= 1)
                s += __shfl_xor_sync(0xffffffffu, s, o, 16);
            float sc = __expf(mr[i] - nm);
            lr[i] = lr[i] * sc + s;
            mr[i] = nm;
            #pragma unroll
            for (int j = 0; j < 4; j++) O[i][j] *= sc;
        }

        __syncthreads();   // everyone done reading Kt
        #pragma unroll
        for (int i = 0; i < 4; i++)
            *(float4*)&KP[(4 * ty + i) * 68 + 4 * tx] =
                make_float4(P[i][0], P[i][1], P[i][2], P[i][3]);
        __syncthreads();

        // Phase 2: O += P V
        #pragma unroll 16
        for (int c = 0; c < 64; c++) {
            float4 v4 = *(const float4*)&Vs[c * 64 + 4 * tx];
            float vv[4] = {v4.x, v4.y, v4.z, v4.w};
            #pragma unroll
            for (int i = 0; i < 4; i++) {
                float p = KP[(4 * ty + i) * 68 + c];
                #pragma unroll
                for (int j = 0; j < 4; j++)
                    O[i][j] = fmaf(p, vv[j], O[i][j]);
            }
        }
    }

    // Normalize and write ctx in [B,T,D] layout (ready for Wo GEMM)
    #pragma unroll
    for (int i = 0; i < 4; i++) {
        float inv = 1.0f / lr[i];
        int t = q0 + 4 * ty + i;
        float4 o = make_float4(O[i][0] * inv, O[i][1] * inv,
                               O[i][2] * inv, O[i][3] * inv);
        *(float4*)&ctx[((size_t)b * Tt + t) * Dd + h * HDIM + 4 * tx] = o;
    }
}

// ---------------------------------------------------------------------------
extern "C" void kernel_launch(void* const* d_in, const int* in_sizes, int n_in,
                              void* d_out, int out_size)
{
    const float* x  = (const float*)d_in[0];
    const float* Wq = (const float*)d_in[1];
    const float* Wk = (const float*)d_in[2];
    const float* Wv = (const float*)d_in[3];
    const float* Wo = (const float*)d_in[4];
    const float* bo = (const float*)d_in[5];
    float* out = (float*)d_out;

    float *pq, *pk, *pv, *pctx;
    cudaGetSymbolAddress((void**)&pq,   g_q);
    cudaGetSymbolAddress((void**)&pk,   g_k);
    cudaGetSymbolAddress((void**)&pv,   g_v);
    cudaGetSymbolAddress((void**)&pctx, g_ctx);

    const int SMEM = (64 * 68 * 2 + 64 * 64) * (int)sizeof(float);  // 51200B
    cudaFuncSetAttribute(flash64, cudaFuncAttributeMaxDynamicSharedMemorySize, SMEM);

    dim3 gg(Dd / 64, MTOT / 64);   // (16, 64)

    gemm64<<<gg, 256>>>(x, Wq, pq, nullptr, 1);
    gemm64<<<gg, 256>>>(x, Wk, pk, nullptr, 1);
    gemm64<<<gg, 256>>>(x, Wv, pv, nullptr, 1);

    flash64<<<dim3(Tt / 64, Hh, Bb), 256, SMEM>>>(pq, pk, pv, pctx);

    gemm64<<<gg, 256>>>(pctx, Wo, out, bo, 0);
}

// round 2
// speedup vs baseline: 2.2106x; 2.2106x over previous
#include <cuda_runtime.h>

#define Bb   2
#define Tt   2048
#define Dd   1024
#define Hh   16
#define HDIM 64
#define MTOT (Bb*Tt)        // 4096

// Scratch (allocation-free rule: __device__ globals)
__device__ float g_q[Bb*Hh*Tt*HDIM];
__device__ float g_k[Bb*Hh*Tt*HDIM];
__device__ float g_v[Bb*Hh*Tt*HDIM];
__device__ float g_ctx[Bb*Tt*Dd];

// ---- tf32 helpers -----------------------------------------------------------
__device__ __forceinline__ unsigned rtf_u(float x) {
    unsigned u; asm("cvt.rna.tf32.f32 %0, %1;" : "=r"(u) : "f"(x)); return u;
}
__device__ __forceinline__ float rtf(float x) { return __uint_as_float(rtf_u(x)); }
__device__ __forceinline__ unsigned f2u(float x) { return __float_as_uint(x); }

// mma.sync m16n8k8 tf32: D += A*B.
// A frag: a0=(g,tIG) a1=(g+8,tIG) a2=(g,tIG+4) a3=(g+8,tIG+4)
// B frag: b0=(k=tIG,n=g) b1=(k=tIG+4,n=g)
// C frag: c0=(g,2tIG) c1=(g,2tIG+1) c2=(g+8,2tIG) c3=(g+8,2tIG+1)
__device__ __forceinline__ void mma8(float* d, const unsigned* a, const unsigned* b) {
    asm volatile(
        "mma.sync.aligned.m16n8k8.row.col.f32.tf32.tf32.f32 "
        "{%0,%1,%2,%3}, {%4,%5,%6,%7}, {%8,%9}, {%0,%1,%2,%3};\n"
        : "+f"(d[0]), "+f"(d[1]), "+f"(d[2]), "+f"(d[3])
        : "r"(a[0]), "r"(a[1]), "r"(a[2]), "r"(a[3]), "r"(b[0]), "r"(b[1]));
}

// ---------------------------------------------------------------------------
// GEMM (tf32 tensor): C = A[M,1024] * W[1024,1024] (+bias)
// Block tile 128x64, BK=32, 256 threads = 8 warps, warp tile 32x32.
// mode 0: row-major [M,1024] + bias     mode 1: head-split [B,H,T,64]
// ---------------------------------------------------------------------------
__global__ void gemm_mma(const float* __restrict__ A, const float* __restrict__ W,
                         float* __restrict__ C, const float* __restrict__ bias,
                         int mode)
{
    __shared__ float As[128][36];   // [m][k], stride 36 -> (4g+tIG) conflict-free
    __shared__ float Ws[32][68];    // [k][n], stride 68 -> (4tIG+g) conflict-free

    const int tid  = threadIdx.x;
    const int lane = tid & 31, warp = tid >> 5;
    const int g = lane >> 2, tg = lane & 3;
    const int wm = warp & 3;        // 4 warp-rows of 32
    const int wn = warp >> 2;       // 2 warp-cols of 32
    const int m0 = blockIdx.y * 128;
    const int n0 = blockIdx.x * 64;

    float acc[2][4][4];
    #pragma unroll
    for (int i = 0; i < 2; i++)
        #pragma unroll
        for (int j = 0; j < 4; j++)
            #pragma unroll
            for (int l = 0; l < 4; l++) acc[i][j][l] = 0.f;

    for (int k0 = 0; k0 < 1024; k0 += 32) {
        // A tile 128x32 (1024 float4, 4/thread), rounded to tf32 at store
        #pragma unroll
        for (int i = 0; i < 4; i++) {
            int idx = i * 256 + tid;
            int r = idx >> 3, c4 = (idx & 7) * 4;
            float4 v = *(const float4*)&A[(size_t)(m0 + r) * 1024 + k0 + c4];
            float4 o = make_float4(rtf(v.x), rtf(v.y), rtf(v.z), rtf(v.w));
            *(float4*)&As[r][c4] = o;
        }
        // W tile 32x64 (512 float4, 2/thread)
        #pragma unroll
        for (int i = 0; i < 2; i++) {
            int idx = i * 256 + tid;
            int r = idx >> 4, c4 = (idx & 15) * 4;
            float4 v = *(const float4*)&W[(size_t)(k0 + r) * 1024 + n0 + c4];
            float4 o = make_float4(rtf(v.x), rtf(v.y), rtf(v.z), rtf(v.w));
            *(float4*)&Ws[r][c4] = o;
        }
        __syncthreads();

        #pragma unroll
        for (int kk = 0; kk < 32; kk += 8) {
            unsigned a[2][4];
            #pragma unroll
            for (int mt = 0; mt < 2; mt++) {
                int rb = wm * 32 + mt * 16;
                a[mt][0] = f2u(As[rb + g    ][kk + tg    ]);
                a[mt][1] = f2u(As[rb + g + 8][kk + tg    ]);
                a[mt][2] = f2u(As[rb + g    ][kk + tg + 4]);
                a[mt][3] = f2u(As[rb + g + 8][kk + tg + 4]);
            }
            #pragma unroll
            for (int nt = 0; nt < 4; nt++) {
                int nb = wn * 32 + nt * 8;
                unsigned b[2];
                b[0] = f2u(Ws[kk + tg    ][nb + g]);
                b[1] = f2u(Ws[kk + tg + 4][nb + g]);
                mma8(acc[0][nt], a[0], b);
                mma8(acc[1][nt], a[1], b);
            }
        }
        __syncthreads();
    }

    // Epilogue
    #pragma unroll
    for (int mt = 0; mt < 2; mt++) {
        #pragma unroll
        for (int nt = 0; nt < 4; nt++) {
            int colL = wn * 32 + nt * 8 + 2 * tg;       // local col (pair)
            int rA = m0 + wm * 32 + mt * 16 + g;
            int rB = rA + 8;
            float c0 = acc[mt][nt][0], c1 = acc[mt][nt][1];
            float c2 = acc[mt][nt][2], c3 = acc[mt][nt][3];
            if (mode == 0) {
                float b0 = bias[n0 + colL], b1 = bias[n0 + colL + 1];
                *(float2*)&C[(size_t)rA * 1024 + n0 + colL] = make_float2(c0 + b0, c1 + b1);
                *(float2*)&C[(size_t)rB * 1024 + n0 + colL] = make_float2(c2 + b0, c3 + b1);
            } else {
                int h = blockIdx.x;                      // BN==64==HDIM
                int bA = rA >> 11, tA = rA & 2047;
                int bB = rB >> 11, tB = rB & 2047;
                size_t baseA = (size_t)bA * (Hh*Tt*HDIM) + (size_t)h * (Tt*HDIM) + (size_t)tA * HDIM + colL;
                size_t baseB = (size_t)bB * (Hh*Tt*HDIM) + (size_t)h * (Tt*HDIM) + (size_t)tB * HDIM + colL;
                *(float2*)&C[baseA] = make_float2(c0, c1);
                *(float2*)&C[baseB] = make_float2(c2, c3);
            }
        }
    }
}

// ---------------------------------------------------------------------------
// Flash attention (tf32 tensor): block = 64 queries of one (b,h), 4 warps.
// Each warp owns 16 q-rows. S=Q*K^T and O+=P*V via mma; online softmax on
// C-fragments; P round-trips through smem (reuses K buffer).
// smem: Qs[64][68] | Ks/Ps[64][68] | Vs[64][68]  = 52224 B dynamic
// ---------------------------------------------------------------------------
__global__ void flash_mma(const float* __restrict__ q, const float* __restrict__ k,
                          const float* __restrict__ v, float* __restrict__ ctx)
{
    extern __shared__ float sm[];
    float* Qs = sm;               // [64][68]
    float* Ks = sm + 64 * 68;     // [64][68], reused as P
    float* Vs = Ks + 64 * 68;     // [64][68]

    const int tid  = threadIdx.x;
    const int lane = tid & 31, warp = tid >> 5;
    const int g = lane >> 2, tg = lane & 3;
    const int wq = warp * 16;                       // warp's q-row base
    const int qt = blockIdx.x, h = blockIdx.y, b = blockIdx.z;
    const int q0 = qt * 64;

    const size_t bh = (size_t)(b * Hh + h) * (Tt * HDIM);
    const float* qb = q + bh;
    const float* kb = k + bh;
    const float* vb = v + bh;

    // Q tile (scaled by 1/sqrt(64), tf32-rounded)
    #pragma unroll
    for (int i = 0; i < 8; i++) {
        int idx = i * 128 + tid;
        int r = idx >> 4, c4 = (idx & 15) * 4;
        float4 x = *(const float4*)&qb[(size_t)(q0 + r) * HDIM + c4];
        *(float4*)&Qs[r * 68 + c4] = make_float4(rtf(x.x * 0.125f), rtf(x.y * 0.125f),
                                                 rtf(x.z * 0.125f), rtf(x.w * 0.125f));
    }

    float mrow[2] = {-1e30f, -1e30f};
    float lrow[2] = {0.f, 0.f};
    float O[8][4];
    #pragma unroll
    for (int nt = 0; nt < 8; nt++)
        #pragma unroll
        for (int j = 0; j < 4; j++) O[nt][j] = 0.f;

    for (int kt = 0; kt <= qt; kt++) {
        const int k0 = kt * 64;
        __syncthreads();                       // prior PV readers done
        #pragma unroll
        for (int i = 0; i < 8; i++) {
            int idx = i * 128 + tid;
            int r = idx >> 4, c4 = (idx & 15) * 4;
            float4 kx = *(const float4*)&kb[(size_t)(k0 + r) * HDIM + c4];
            float4 vx = *(const float4*)&vb[(size_t)(k0 + r) * HDIM + c4];
            *(float4*)&Ks[r * 68 + c4] = make_float4(rtf(kx.x), rtf(kx.y), rtf(kx.z), rtf(kx.w));
            *(float4*)&Vs[r * 68 + c4] = make_float4(rtf(vx.x), rtf(vx.y), rtf(vx.z), rtf(vx.w));
        }
        __syncthreads();

        // S = Q K^T   (16 x 64 per warp)
        float S[8][4];
        #pragma unroll
        for (int nt = 0; nt < 8; nt++)
            #pragma unroll
            for (int j = 0; j < 4; j++) S[nt][j] = 0.f;

        #pragma unroll
        for (int kk = 0; kk < 64; kk += 8) {
            unsigned a[4];
            a[0] = f2u(Qs[(wq + g    ) * 68 + kk + tg    ]);
            a[1] = f2u(Qs[(wq + g + 8) * 68 + kk + tg    ]);
            a[2] = f2u(Qs[(wq + g    ) * 68 + kk + tg + 4]);
            a[3] = f2u(Qs[(wq + g + 8) * 68 + kk + tg + 4]);
            #pragma unroll
            for (int nt = 0; nt < 8; nt++) {
                unsigned bb[2];
                bb[0] = f2u(Ks[(nt * 8 + g) * 68 + kk + tg    ]);
                bb[1] = f2u(Ks[(nt * 8 + g) * 68 + kk + tg + 4]);
                mma8(S[nt], a, bb);
            }
        }

        // Causal mask on diagonal tile
        if (kt == qt) {
            int qA = q0 + wq + g, qB = qA + 8;
            #pragma unroll
            for (int nt = 0; nt < 8; nt++) {
                int c = k0 + nt * 8 + 2 * tg;
                if (c     > qA) S[nt][0] = -1e30f;
                if (c + 1 > qA) S[nt][1] = -1e30f;
                if (c     > qB) S[nt][2] = -1e30f;
                if (c + 1 > qB) S[nt][3] = -1e30f;
            }
        }

        // Online softmax (rows g and g+8)
        float mA = -1e30f, mB = -1e30f;
        #pragma unroll
        for (int nt = 0; nt < 8; nt++) {
            mA = fmaxf(mA, fmaxf(S[nt][0], S[nt][1]));
            mB = fmaxf(mB, fmaxf(S[nt][2], S[nt][3]));
        }
        #pragma unroll
        for (int o = 1; o <= 2; o <<= 1) {
            mA = fmaxf(mA, __shfl_xor_sync(0xffffffffu, mA, o));
            mB = fmaxf(mB, __shfl_xor_sync(0xffffffffu, mB, o));
        }
        float nmA = fmaxf(mrow[0], mA), nmB = fmaxf(mrow[1], mB);
        float sA = 0.f, sB = 0.f;
        #pragma unroll
        for (int nt = 0; nt < 8; nt++) {
            S[nt][0] = __expf(S[nt][0] - nmA);
            S[nt][1] = __expf(S[nt][1] - nmA);
            S[nt][2] = __expf(S[nt][2] - nmB);
            S[nt][3] = __expf(S[nt][3] - nmB);
            sA += S[nt][0] + S[nt][1];
            sB += S[nt][2] + S[nt][3];
        }
        #pragma unroll
        for (int o = 1; o <= 2; o <<= 1) {
            sA += __shfl_xor_sync(0xffffffffu, sA, o);
            sB += __shfl_xor_sync(0xffffffffu, sB, o);
        }
        float scA = __expf(mrow[0] - nmA), scB = __expf(mrow[1] - nmB);
        lrow[0] = lrow[0] * scA + sA;  mrow[0] = nmA;
        lrow[1] = lrow[1] * scB + sB;  mrow[1] = nmB;
        #pragma unroll
        for (int nt = 0; nt < 8; nt++) {
            O[nt][0] *= scA; O[nt][1] *= scA;
            O[nt][2] *= scB; O[nt][3] *= scB;
        }

        __syncthreads();               // all warps done reading Ks
        // Store P (tf32-rounded) into Ks buffer
        #pragma unroll
        for (int nt = 0; nt < 8; nt++) {
            int c = nt * 8 + 2 * tg;
            *(float2*)&Ks[(wq + g    ) * 68 + c] = make_float2(rtf(S[nt][0]), rtf(S[nt][1]));
            *(float2*)&Ks[(wq + g + 8) * 68 + c] = make_float2(rtf(S[nt][2]), rtf(S[nt][3]));
        }
        __syncthreads();

        // O += P V   (k = 64 key columns)
        #pragma unroll
        for (int kk = 0; kk < 64; kk += 8) {
            unsigned a[4];
            a[0] = f2u(Ks[(wq + g    ) * 68 + kk + tg    ]);
            a[1] = f2u(Ks[(wq + g + 8) * 68 + kk + tg    ]);
            a[2] = f2u(Ks[(wq + g    ) * 68 + kk + tg + 4]);
            a[3] = f2u(Ks[(wq + g + 8) * 68 + kk + tg + 4]);
            #pragma unroll
            for (int nt = 0; nt < 8; nt++) {
                unsigned bb[2];
                bb[0] = f2u(Vs[(kk + tg    ) * 68 + nt * 8 + g]);
                bb[1] = f2u(Vs[(kk + tg + 4) * 68 + nt * 8 + g]);
                mma8(O[nt], a, bb);
            }
        }
    }

    // Normalize + write ctx [B,T,D]
    float invA = 1.0f / lrow[0], invB = 1.0f / lrow[1];
    int tA = q0 + wq + g, tB = tA + 8;
    #pragma unroll
    for (int nt = 0; nt < 8; nt++) {
        int c = h * HDIM + nt * 8 + 2 * tg;
        *(float2*)&ctx[((size_t)b * Tt + tA) * Dd + c] =
            make_float2(O[nt][0] * invA, O[nt][1] * invA);
        *(float2*)&ctx[((size_t)b * Tt + tB) * Dd + c] =
            make_float2(O[nt][2] * invB, O[nt][3] * invB);
    }
}

// ---------------------------------------------------------------------------
extern "C" void kernel_launch(void* const* d_in, const int* in_sizes, int n_in,
                              void* d_out, int out_size)
{
    const float* x  = (const float*)d_in[0];
    const float* Wq = (const float*)d_in[1];
    const float* Wk = (const float*)d_in[2];
    const float* Wv = (const float*)d_in[3];
    const float* Wo = (const float*)d_in[4];
    const float* bo = (const float*)d_in[5];
    float* out = (float*)d_out;

    float *pq, *pk, *pv, *pctx;
    cudaGetSymbolAddress((void**)&pq,   g_q);
    cudaGetSymbolAddress((void**)&pk,   g_k);
    cudaGetSymbolAddress((void**)&pv,   g_v);
    cudaGetSymbolAddress((void**)&pctx, g_ctx);

    const int SMEM = 3 * 64 * 68 * (int)sizeof(float);   // 52224 B
    cudaFuncSetAttribute(flash_mma, cudaFuncAttributeMaxDynamicSharedMemorySize, SMEM);

    dim3 gg(Dd / 64, MTOT / 128);   // (16, 32)

    gemm_mma<<<gg, 256>>>(x, Wq, pq, nullptr, 1);
    gemm_mma<<<gg, 256>>>(x, Wk, pk, nullptr, 1);
    gemm_mma<<<gg, 256>>>(x, Wv, pv, nullptr, 1);

    flash_mma<<<dim3(Tt / 64, Hh, Bb), 128, SMEM>>>(pq, pk, pv, pctx);

    gemm_mma<<<gg, 256>>>(pctx, Wo, out, bo, 0);
}

// round 3
// speedup vs baseline: 2.7427x; 1.2407x over previous
#include <cuda_runtime.h>

#define Bb   2
#define Tt   2048
#define Dd   1024
#define Hh   16
#define HDIM 64
#define MTOT (Bb*Tt)        // 4096

// Scratch (allocation-free rule: __device__ globals)
__device__ float g_q[Bb*Hh*Tt*HDIM];
__device__ float g_k[Bb*Hh*Tt*HDIM];
__device__ float g_v[Bb*Hh*Tt*HDIM];
__device__ float g_ctx[Bb*Tt*Dd];

// ---- tf32 helpers ---------------------------------------------------------
__device__ __forceinline__ unsigned rtf_u(float x) {
    unsigned u; asm("cvt.rna.tf32.f32 %0, %1;" : "=r"(u) : "f"(x)); return u;
}
__device__ __forceinline__ float rtf(float x) { return __uint_as_float(rtf_u(x)); }
__device__ __forceinline__ unsigned f2u(float x) { return __float_as_uint(x); }
__device__ __forceinline__ float4 cvt4(float4 v) {
    return make_float4(rtf(v.x), rtf(v.y), rtf(v.z), rtf(v.w));
}

// mma.sync m16n8k8 tf32: D += A*B
// A: a0=(g,tg) a1=(g+8,tg) a2=(g,tg+4) a3=(g+8,tg+4)
// B: b0=(k=tg,n=g) b1=(k=tg+4,n=g)
// C: c0=(g,2tg) c1=(g,2tg+1) c2=(g+8,2tg) c3=(g+8,2tg+1)
__device__ __forceinline__ void mma8(float* d, const unsigned* a, const unsigned* b) {
    asm volatile(
        "mma.sync.aligned.m16n8k8.row.col.f32.tf32.tf32.f32 "
        "{%0,%1,%2,%3}, {%4,%5,%6,%7}, {%8,%9}, {%0,%1,%2,%3};\n"
        : "+f"(d[0]), "+f"(d[1]), "+f"(d[2]), "+f"(d[3])
        : "r"(a[0]), "r"(a[1]), "r"(a[2]), "r"(a[3]), "r"(b[0]), "r"(b[1]));
}

// ---------------------------------------------------------------------------
// GEMM (tf32, pipelined): C = A[M,1024]*W[1024,1024] (+bias)
// 128x128 block tile, BK=32, 256 thr = 8 warps (2m x 4n), warp tile 64x32.
// Register-prefetch gmem + 2-stage smem -> ONE __syncthreads per K-iter.
// mode 0: row-major + bias (uses W0/C0).  mode 1: head-split, z selects QKV.
// ---------------------------------------------------------------------------
#define AS_ST (128*36)
#define WS_ST (32*132)
__global__ __launch_bounds__(256, 1)
void gemm_mma(const float* __restrict__ A,
              const float* __restrict__ W0, const float* __restrict__ W1,
              const float* __restrict__ W2,
              float* __restrict__ C0, float* __restrict__ C1,
              float* __restrict__ C2,
              const float* __restrict__ bias, int mode)
{
    extern __shared__ float sh[];
    float* Asm = sh;             // [2][128][36]
    float* Wsm = sh + 2*AS_ST;   // [2][32][132]

    const float* W = (blockIdx.z == 0) ? W0 : (blockIdx.z == 1) ? W1 : W2;
    float*       C = (blockIdx.z == 0) ? C0 : (blockIdx.z == 1) ? C1 : C2;

    const int tid = threadIdx.x;
    const int lane = tid & 31, warp = tid >> 5;
    const int g = lane >> 2, tg = lane & 3;
    const int wm = warp >> 2;       // 0..1  (64 rows)
    const int wn = warp & 3;        // 0..3  (32 cols)
    const int m0 = blockIdx.y * 128;
    const int n0 = blockIdx.x * 128;

    float acc[4][4][4];
    #pragma unroll
    for (int mt = 0; mt < 4; mt++)
        #pragma unroll
        for (int nt = 0; nt < 4; nt++)
            #pragma unroll
            for (int c = 0; c < 4; c++) acc[mt][nt][c] = 0.f;

    float4 pa[4], pb[4];

    // gmem -> regs for K-slice k0
    auto LDG = [&](int k0) {
        #pragma unroll
        for (int i = 0; i < 4; i++) {
            int idx = i * 256 + tid;
            int r = idx >> 3, c4 = (idx & 7) * 4;      // A: 128x32
            pa[i] = *(const float4*)&A[(size_t)(m0 + r) * 1024 + k0 + c4];
        }
        #pragma unroll
        for (int i = 0; i < 4; i++) {
            int idx = i * 256 + tid;
            int r = idx >> 5, c4 = (idx & 31) * 4;     // W: 32x128
            pb[i] = *(const float4*)&W[(size_t)(k0 + r) * 1024 + n0 + c4];
        }
    };
    // regs -> smem stage st (tf32-rounded)
    auto STS = [&](int st) {
        float* Ab = Asm + st * AS_ST;
        float* Wb = Wsm + st * WS_ST;
        #pragma unroll
        for (int i = 0; i < 4; i++) {
            int idx = i * 256 + tid;
            int r = idx >> 3, c4 = (idx & 7) * 4;
            *(float4*)&Ab[r * 36 + c4] = cvt4(pa[i]);
        }
        #pragma unroll
        for (int i = 0; i < 4; i++) {
            int idx = i * 256 + tid;
            int r = idx >> 5, c4 = (idx & 31) * 4;
            *(float4*)&Wb[r * 132 + c4] = cvt4(pb[i]);
        }
    };

    LDG(0); STS(0); __syncthreads();

    for (int it = 0; it < 32; it++) {
        const int st = it & 1;
        if (it < 31) LDG((it + 1) * 32);               // overlap with mma

        const float* Ab = Asm + st * AS_ST;
        const float* Wb = Wsm + st * WS_ST;
        #pragma unroll
        for (int kk = 0; kk < 32; kk += 8) {
            unsigned a[4][4], b[4][2];
            #pragma unroll
            for (int mt = 0; mt < 4; mt++) {
                int rb = wm * 64 + mt * 16;
                a[mt][0] = f2u(Ab[(rb + g    ) * 36 + kk + tg    ]);
                a[mt][1] = f2u(Ab[(rb + g + 8) * 36 + kk + tg    ]);
                a[mt][2] = f2u(Ab[(rb + g    ) * 36 + kk + tg + 4]);
                a[mt][3] = f2u(Ab[(rb + g + 8) * 36 + kk + tg + 4]);
            }
            #pragma unroll
            for (int nt = 0; nt < 4; nt++) {
                int nb = wn * 32 + nt * 8;
                b[nt][0] = f2u(Wb[(kk + tg    ) * 132 + nb + g]);
                b[nt][1] = f2u(Wb[(kk + tg + 4) * 132 + nb + g]);
            }
            #pragma unroll
            for (int mt = 0; mt < 4; mt++)
                #pragma unroll
                for (int nt = 0; nt < 4; nt++)
                    mma8(acc[mt][nt], a[mt], b[nt]);
        }
        if (it < 31) STS(st ^ 1);
        __syncthreads();
    }

    // Epilogue
    #pragma unroll
    for (int mt = 0; mt < 4; mt++) {
        #pragma unroll
        for (int nt = 0; nt < 4; nt++) {
            int colL = wn * 32 + nt * 8 + 2 * tg;
            int rA = m0 + wm * 64 + mt * 16 + g;
            int rB = rA + 8;
            float c0 = acc[mt][nt][0], c1 = acc[mt][nt][1];
            float c2 = acc[mt][nt][2], c3 = acc[mt][nt][3];
            if (mode == 0) {
                float b0 = bias[n0 + colL], b1 = bias[n0 + colL + 1];
                *(float2*)&C[(size_t)rA * 1024 + n0 + colL] = make_float2(c0 + b0, c1 + b1);
                *(float2*)&C[(size_t)rB * 1024 + n0 + colL] = make_float2(c2 + b0, c3 + b1);
            } else {
                int gc = n0 + colL;
                int h = gc >> 6, d = gc & 63;
                int bA = rA >> 11, tA = rA & 2047;
                int bB = rB >> 11, tB = rB & 2047;
                size_t baseA = (size_t)bA * (Hh*Tt*HDIM) + (size_t)h * (Tt*HDIM)
                             + (size_t)tA * HDIM + d;
                size_t baseB = (size_t)bB * (Hh*Tt*HDIM) + (size_t)h * (Tt*HDIM)
                             + (size_t)tB * HDIM + d;
                *(float2*)&C[baseA] = make_float2(c0, c1);
                *(float2*)&C[baseB] = make_float2(c2, c3);
            }
        }
    }
}

// ---------------------------------------------------------------------------
// Flash attention (tf32, pipelined): block = 128 queries of one (b,h),
// 8 warps x 16 q-rows.  K/V tiles of 64 keys, register-prefetched.
// P has its own smem buffer -> warp-local (syncwarp), 2 block syncs / tile.
// Fully-masked warps skip compute.  Heaviest q-tiles launch first.
// smem: Qs[128][68] | Ks[64][68] | Vs[64][68] | Ps[128][68] = 104448 B
// ---------------------------------------------------------------------------
__global__ __launch_bounds__(256, 1)
void flash_mma(const float* __restrict__ q, const float* __restrict__ k,
               const float* __restrict__ v, float* __restrict__ ctx)
{
    extern __shared__ float sm[];
    float* Qs = sm;                   // [128][68]
    float* Ks = Qs + 128 * 68;        // [64][68]
    float* Vs = Ks + 64 * 68;         // [64][68]
    float* Ps = Vs + 64 * 68;         // [128][68]

    const int tid  = threadIdx.x;
    const int lane = tid & 31, warp = tid >> 5;
    const int g = lane >> 2, tg = lane & 3;
    const int wq = warp * 16;
    const int qt = (gridDim.x - 1) - blockIdx.x;      // heavy blocks first
    const int h = blockIdx.y, b = blockIdx.z;
    const int q0 = qt * 128;

    const size_t bh = (size_t)(b * Hh + h) * (Tt * HDIM);
    const float* qb = q + bh;
    const float* kb = k + bh;
    const float* vb = v + bh;

    // Q tile (scaled, tf32-rounded)
    #pragma unroll
    for (int i = 0; i < 8; i++) {
        int idx = i * 256 + tid;
        int r = idx >> 4, c4 = (idx & 15) * 4;
        float4 x = *(const float4*)&qb[(size_t)(q0 + r) * HDIM + c4];
        *(float4*)&Qs[r * 68 + c4] = make_float4(rtf(x.x * 0.125f), rtf(x.y * 0.125f),
                                                 rtf(x.z * 0.125f), rtf(x.w * 0.125f));
    }

    float mrow[2] = {-1e30f, -1e30f};
    float lrow[2] = {0.f, 0.f};
    float O[8][4];
    #pragma unroll
    for (int nt = 0; nt < 8; nt++)
        #pragma unroll
        for (int j = 0; j < 4; j++) O[nt][j] = 0.f;

    float4 kr[4], vr[4];
    auto LDKV = [&](int k0) {
        #pragma unroll
        for (int i = 0; i < 4; i++) {
            int idx = i * 256 + tid;
            int r = idx >> 4, c4 = (idx & 15) * 4;
            kr[i] = *(const float4*)&kb[(size_t)(k0 + r) * HDIM + c4];
            vr[i] = *(const float4*)&vb[(size_t)(k0 + r) * HDIM + c4];
        }
    };
    auto STKV = [&]() {
        #pragma unroll
        for (int i = 0; i < 4; i++) {
            int idx = i * 256 + tid;
            int r = idx >> 4, c4 = (idx & 15) * 4;
            *(float4*)&Ks[r * 68 + c4] = cvt4(kr[i]);
            *(float4*)&Vs[r * 68 + c4] = cvt4(vr[i]);
        }
    };

    const int ktmax = 2 * qt + 1;     // K tiles 0..ktmax (64 keys each)
    LDKV(0);

    for (int kt = 0; kt <= ktmax; kt++) {
        const int k0 = kt * 64;
        __syncthreads();              // prior tile's readers done
        STKV();
        __syncthreads();
        if (kt < ktmax) LDKV(k0 + 64);            // overlap with compute

        if (k0 <= q0 + wq + 15) {                 // warp has unmasked rows
            // S = Q K^T  (16 x 64)
            float S[8][4];
            #pragma unroll
            for (int nt = 0; nt < 8; nt++)
                #pragma unroll
                for (int j = 0; j < 4; j++) S[nt][j] = 0.f;

            #pragma unroll
            for (int kk = 0; kk < 64; kk += 8) {
                unsigned a[4];
                a[0] = f2u(Qs[(wq + g    ) * 68 + kk + tg    ]);
                a[1] = f2u(Qs[(wq + g + 8) * 68 + kk + tg    ]);
                a[2] = f2u(Qs[(wq + g    ) * 68 + kk + tg + 4]);
                a[3] = f2u(Qs[(wq + g + 8) * 68 + kk + tg + 4]);
                #pragma unroll
                for (int nt = 0; nt < 8; nt++) {
                    unsigned bb[2];
                    bb[0] = f2u(Ks[(nt * 8 + g) * 68 + kk + tg    ]);
                    bb[1] = f2u(Ks[(nt * 8 + g) * 68 + kk + tg + 4]);
                    mma8(S[nt], a, bb);
                }
            }

            // causal mask (only when tile straddles the diagonal)
            if (k0 + 63 > q0 + wq) {
                int qA = q0 + wq + g, qB = qA + 8;
                #pragma unroll
                for (int nt = 0; nt < 8; nt++) {
                    int c = k0 + nt * 8 + 2 * tg;
                    if (c     > qA) S[nt][0] = -1e30f;
                    if (c + 1 > qA) S[nt][1] = -1e30f;
                    if (c     > qB) S[nt][2] = -1e30f;
                    if (c + 1 > qB) S[nt][3] = -1e30f;
                }
            }

            // online softmax (rows g, g+8)
            float mA = -1e30f, mB = -1e30f;
            #pragma unroll
            for (int nt = 0; nt < 8; nt++) {
                mA = fmaxf(mA, fmaxf(S[nt][0], S[nt][1]));
                mB = fmaxf(mB, fmaxf(S[nt][2], S[nt][3]));
            }
            #pragma unroll
            for (int o = 1; o <= 2; o <<= 1) {
                mA = fmaxf(mA, __shfl_xor_sync(0xffffffffu, mA, o));
                mB = fmaxf(mB, __shfl_xor_sync(0xffffffffu, mB, o));
            }
            float nmA = fmaxf(mrow[0], mA), nmB = fmaxf(mrow[1], mB);
            float sA = 0.f, sB = 0.f;
            #pragma unroll
            for (int nt = 0; nt < 8; nt++) {
                S[nt][0] = __expf(S[nt][0] - nmA);
                S[nt][1] = __expf(S[nt][1] - nmA);
                S[nt][2] = __expf(S[nt][2] - nmB);
                S[nt][3] = __expf(S[nt][3] - nmB);
                sA += S[nt][0] + S[nt][1];
                sB += S[nt][2] + S[nt][3];
            }
            #pragma unroll
            for (int o = 1; o <= 2; o <<= 1) {
                sA += __shfl_xor_sync(0xffffffffu, sA, o);
                sB += __shfl_xor_sync(0xffffffffu, sB, o);
            }
            float scA = __expf(mrow[0] - nmA), scB = __expf(mrow[1] - nmB);
            lrow[0] = lrow[0] * scA + sA;  mrow[0] = nmA;
            lrow[1] = lrow[1] * scB + sB;  mrow[1] = nmB;
            #pragma unroll
            for (int nt = 0; nt < 8; nt++) {
                O[nt][0] *= scA; O[nt][1] *= scA;
                O[nt][2] *= scB; O[nt][3] *= scB;
            }

            // P -> warp-private smem rows (no block sync needed)
            #pragma unroll
            for (int nt = 0; nt < 8; nt++) {
                int c = nt * 8 + 2 * tg;
                *(float2*)&Ps[(wq + g    ) * 68 + c] = make_float2(rtf(S[nt][0]), rtf(S[nt][1]));
                *(float2*)&Ps[(wq + g + 8) * 68 + c] = make_float2(rtf(S[nt][2]), rtf(S[nt][3]));
            }
            __syncwarp();

            // O += P V
            #pragma unroll
            for (int kk = 0; kk < 64; kk += 8) {
                unsigned a[4];
                a[0] = f2u(Ps[(wq + g    ) * 68 + kk + tg    ]);
                a[1] = f2u(Ps[(wq + g + 8) * 68 + kk + tg    ]);
                a[2] = f2u(Ps[(wq + g    ) * 68 + kk + tg + 4]);
                a[3] = f2u(Ps[(wq + g + 8) * 68 + kk + tg + 4]);
                #pragma unroll
                for (int nt = 0; nt < 8; nt++) {
                    unsigned bb[2];
                    bb[0] = f2u(Vs[(kk + tg    ) * 68 + nt * 8 + g]);
                    bb[1] = f2u(Vs[(kk + tg + 4) * 68 + nt * 8 + g]);
                    mma8(O[nt], a, bb);
                }
            }
        }
    }

    // normalize + write ctx [B,T,D]
    float invA = 1.0f / lrow[0], invB = 1.0f / lrow[1];
    int tA = q0 + wq + g, tB = tA + 8;
    #pragma unroll
    for (int nt = 0; nt < 8; nt++) {
        int c = h * HDIM + nt * 8 + 2 * tg;
        *(float2*)&ctx[((size_t)b * Tt + tA) * Dd + c] =
            make_float2(O[nt][0] * invA, O[nt][1] * invA);
        *(float2*)&ctx[((size_t)b * Tt + tB) * Dd + c] =
            make_float2(O[nt][2] * invB, O[nt][3] * invB);
    }
}

// ---------------------------------------------------------------------------
extern "C" void kernel_launch(void* const* d_in, const int* in_sizes, int n_in,
                              void* d_out, int out_size)
{
    const float* x  = (const float*)d_in[0];
    const float* Wq = (const float*)d_in[1];
    const float* Wk = (const float*)d_in[2];
    const float* Wv = (const float*)d_in[3];
    const float* Wo = (const float*)d_in[4];
    const float* bo = (const float*)d_in[5];
    float* out = (float*)d_out;

    float *pq, *pk, *pv, *pctx;
    cudaGetSymbolAddress((void**)&pq,   g_q);
    cudaGetSymbolAddress((void**)&pk,   g_k);
    cudaGetSymbolAddress((void**)&pv,   g_v);
    cudaGetSymbolAddress((void**)&pctx, g_ctx);

    const int GSMEM = (2*AS_ST + 2*WS_ST) * (int)sizeof(float);   // 70656
    const int FSMEM = (128*68 + 64*68 + 64*68 + 128*68) * (int)sizeof(float); // 104448
    cudaFuncSetAttribute(gemm_mma,  cudaFuncAttributeMaxDynamicSharedMemorySize, GSMEM);
    cudaFuncSetAttribute(flash_mma, cudaFuncAttributeMaxDynamicSharedMemorySize, FSMEM);

    // QKV fused: grid z selects the projection
    gemm_mma<<<dim3(Dd/128, MTOT/128, 3), 256, GSMEM>>>(
        x, Wq, Wk, Wv, pq, pk, pv, nullptr, 1);

    flash_mma<<<dim3(Tt/128, Hh, Bb), 256, FSMEM>>>(pq, pk, pv, pctx);

    gemm_mma<<<dim3(Dd/128, MTOT/128, 1), 256, GSMEM>>>(
        pctx, Wo, nullptr, nullptr, out, nullptr, nullptr, bo, 0);
}

// round 4
// speedup vs baseline: 2.8243x; 1.0298x over previous
#include <cuda_runtime.h>

#define Bb   2
#define Tt   2048
#define Dd   1024
#define Hh   16
#define HDIM 64
#define MTOT (Bb*Tt)        // 4096

// Scratch (allocation-free rule: __device__ globals)
__device__ float g_q[Bb*Hh*Tt*HDIM];
__device__ float g_k[Bb*Hh*Tt*HDIM];
__device__ float g_v[Bb*Hh*Tt*HDIM];
__device__ float g_ctx[Bb*Tt*Dd];
__device__ float g_xr[MTOT*Dd];        // tf32-rounded x
__device__ float g_wr[4][Dd*Dd];       // tf32-rounded Wq,Wk,Wv,Wo

// ---- tf32 helpers ---------------------------------------------------------
__device__ __forceinline__ unsigned rtf_u(float x) {
    unsigned u; asm("cvt.rna.tf32.f32 %0, %1;" : "=r"(u) : "f"(x)); return u;
}
__device__ __forceinline__ float rtf(float x) { return __uint_as_float(rtf_u(x)); }
__device__ __forceinline__ unsigned f2u(float x) { return __float_as_uint(x); }
__device__ __forceinline__ float4 cvt4(float4 v) {
    return make_float4(rtf(v.x), rtf(v.y), rtf(v.z), rtf(v.w));
}
__device__ __forceinline__ void cpasync16(void* dst, const void* src) {
    unsigned s = (unsigned)__cvta_generic_to_shared(dst);
    asm volatile("cp.async.cg.shared.global [%0], [%1], 16;\n" :: "r"(s), "l"(src));
}

// mma.sync m16n8k8 tf32: D += A*B
// A: a0=(g,tg) a1=(g+8,tg) a2=(g,tg+4) a3=(g+8,tg+4)
// B: b0=(k=tg,n=g) b1=(k=tg+4,n=g)
// C: c0=(g,2tg) c1=(g,2tg+1) c2=(g+8,2tg) c3=(g+8,2tg+1)
__device__ __forceinline__ void mma8(float* d, const unsigned* a, const unsigned* b) {
    asm volatile(
        "mma.sync.aligned.m16n8k8.row.col.f32.tf32.tf32.f32 "
        "{%0,%1,%2,%3}, {%4,%5,%6,%7}, {%8,%9}, {%0,%1,%2,%3};\n"
        : "+f"(d[0]), "+f"(d[1]), "+f"(d[2]), "+f"(d[3])
        : "r"(a[0]), "r"(a[1]), "r"(a[2]), "r"(a[3]), "r"(b[0]), "r"(b[1]));
}

// ---------------------------------------------------------------------------
// Pre-round x and the 4 weight matrices to tf32 values (kept in fp32).
// ---------------------------------------------------------------------------
__global__ void preround(const float* __restrict__ x,  const float* __restrict__ wq,
                         const float* __restrict__ wk, const float* __restrict__ wv,
                         const float* __restrict__ wo)
{
    int z = blockIdx.y;
    const float* s; float* d; int n;
    if (z == 0) { s = x;  d = g_xr;    n = MTOT*Dd; }
    else {
        s = (z == 1) ? wq : (z == 2) ? wk : (z == 3) ? wv : wo;
        d = g_wr[z-1]; n = Dd*Dd;
    }
    int i = (blockIdx.x * blockDim.x + threadIdx.x) * 4;
    if (i < n) *(float4*)&d[i] = cvt4(*(const float4*)&s[i]);
}

// ---------------------------------------------------------------------------
// GEMM (tf32, cp.async 3-stage): C = A[M,1024]*W[1024,1024] (+bias)
// A,W pre-rounded.  128x128 tile, BK=32, 256 thr = 8 warps (2m x 4n),
// warp tile 64x32.  2 CTAs/SM.
// mode 0: row-major + bias.  mode 1: head-split (rtf output), z selects QKV.
// ---------------------------------------------------------------------------
#define AS_ST (128*36)
#define WS_ST (32*132)
#define STG 3
__global__ __launch_bounds__(256, 2)
void gemm_mma(const float* __restrict__ A,
              const float* __restrict__ W0, const float* __restrict__ W1,
              const float* __restrict__ W2,
              float* __restrict__ C0, float* __restrict__ C1,
              float* __restrict__ C2,
              const float* __restrict__ bias, int mode)
{
    extern __shared__ float sh[];
    float* Asm = sh;                 // [STG][128][36]
    float* Wsm = sh + STG*AS_ST;     // [STG][32][132]

    const float* W = (blockIdx.z == 0) ? W0 : (blockIdx.z == 1) ? W1 : W2;
    float*       C = (blockIdx.z == 0) ? C0 : (blockIdx.z == 1) ? C1 : C2;

    const int tid = threadIdx.x;
    const int lane = tid & 31, warp = tid >> 5;
    const int g = lane >> 2, tg = lane & 3;
    const int wm = warp >> 2;       // 0..1  (64 rows)
    const int wn = warp & 3;        // 0..3  (32 cols)
    const int m0 = blockIdx.y * 128;
    const int n0 = blockIdx.x * 128;

    float acc[4][4][4];
    #pragma unroll
    for (int mt = 0; mt < 4; mt++)
        #pragma unroll
        for (int nt = 0; nt < 4; nt++)
            #pragma unroll
            for (int c = 0; c < 4; c++) acc[mt][nt][c] = 0.f;

    auto ISSUE = [&](int it) {
        const int k0 = it * 32;
        float* Ab = Asm + (it % STG) * AS_ST;
        float* Wb = Wsm + (it % STG) * WS_ST;
        #pragma unroll
        for (int i = 0; i < 4; i++) {
            int idx = i * 256 + tid;
            int r = idx >> 3, c4 = (idx & 7) * 4;      // A: 128x32
            cpasync16(&Ab[r * 36 + c4], &A[(size_t)(m0 + r) * 1024 + k0 + c4]);
        }
        #pragma unroll
        for (int i = 0; i < 4; i++) {
            int idx = i * 256 + tid;
            int r = idx >> 5, c4 = (idx & 31) * 4;     // W: 32x128
            cpasync16(&Wb[r * 132 + c4], &W[(size_t)(k0 + r) * 1024 + n0 + c4]);
        }
    };

    ISSUE(0); asm volatile("cp.async.commit_group;\n");
    ISSUE(1); asm volatile("cp.async.commit_group;\n");

    for (int it = 0; it < 32; it++) {
        if (it + 2 < 32) ISSUE(it + 2);
        asm volatile("cp.async.commit_group;\n");
        asm volatile("cp.async.wait_group 2;\n");
        __syncthreads();

        const float* Ab = Asm + (it % STG) * AS_ST;
        const float* Wb = Wsm + (it % STG) * WS_ST;
        #pragma unroll
        for (int kk = 0; kk < 32; kk += 8) {
            unsigned a[4][4], b[4][2];
            #pragma unroll
            for (int mt = 0; mt < 4; mt++) {
                int rb = wm * 64 + mt * 16;
                a[mt][0] = f2u(Ab[(rb + g    ) * 36 + kk + tg    ]);
                a[mt][1] = f2u(Ab[(rb + g + 8) * 36 + kk + tg    ]);
                a[mt][2] = f2u(Ab[(rb + g    ) * 36 + kk + tg + 4]);
                a[mt][3] = f2u(Ab[(rb + g + 8) * 36 + kk + tg + 4]);
            }
            #pragma unroll
            for (int nt = 0; nt < 4; nt++) {
                int nb = wn * 32 + nt * 8;
                b[nt][0] = f2u(Wb[(kk + tg    ) * 132 + nb + g]);
                b[nt][1] = f2u(Wb[(kk + tg + 4) * 132 + nb + g]);
            }
            #pragma unroll
            for (int mt = 0; mt < 4; mt++)
                #pragma unroll
                for (int nt = 0; nt < 4; nt++)
                    mma8(acc[mt][nt], a[mt], b[nt]);
        }
        __syncthreads();
    }

    // Epilogue
    #pragma unroll
    for (int mt = 0; mt < 4; mt++) {
        #pragma unroll
        for (int nt = 0; nt < 4; nt++) {
            int colL = wn * 32 + nt * 8 + 2 * tg;
            int rA = m0 + wm * 64 + mt * 16 + g;
            int rB = rA + 8;
            float c0 = acc[mt][nt][0], c1 = acc[mt][nt][1];
            float c2 = acc[mt][nt][2], c3 = acc[mt][nt][3];
            if (mode == 0) {
                float b0 = bias[n0 + colL], b1 = bias[n0 + colL + 1];
                *(float2*)&C[(size_t)rA * 1024 + n0 + colL] = make_float2(c0 + b0, c1 + b1);
                *(float2*)&C[(size_t)rB * 1024 + n0 + colL] = make_float2(c2 + b0, c3 + b1);
            } else {
                int gc = n0 + colL;
                int h = gc >> 6, d = gc & 63;
                int bA = rA >> 11, tA = rA & 2047;
                int bB = rB >> 11, tB = rB & 2047;
                size_t baseA = (size_t)bA * (Hh*Tt*HDIM) + (size_t)h * (Tt*HDIM)
                             + (size_t)tA * HDIM + d;
                size_t baseB = (size_t)bB * (Hh*Tt*HDIM) + (size_t)h * (Tt*HDIM)
                             + (size_t)tB * HDIM + d;
                *(float2*)&C[baseA] = make_float2(rtf(c0), rtf(c1));
                *(float2*)&C[baseB] = make_float2(rtf(c2), rtf(c3));
            }
        }
    }
}

// ---------------------------------------------------------------------------
// Flash attention (tf32): block = 128 queries of one (b,h), 8 warps x 16 rows.
// q/k/v are pre-rounded by the QKV GEMM epilogue -> no conversions here.
// 2 CTAs/SM.  smem: Qs[128][68] | Ks[64][68] | Vs[64][68] | Ps[128][68]
// ---------------------------------------------------------------------------
__global__ __launch_bounds__(256, 2)
void flash_mma(const float* __restrict__ q, const float* __restrict__ k,
               const float* __restrict__ v, float* __restrict__ ctx)
{
    extern __shared__ float sm[];
    float* Qs = sm;                   // [128][68]
    float* Ks = Qs + 128 * 68;        // [64][68]
    float* Vs = Ks + 64 * 68;         // [64][68]
    float* Ps = Vs + 64 * 68;         // [128][68]

    const int tid  = threadIdx.x;
    const int lane = tid & 31, warp = tid >> 5;
    const int g = lane >> 2, tg = lane & 3;
    const int wq = warp * 16;
    const int qt = (gridDim.x - 1) - blockIdx.x;      // heavy blocks first
    const int h = blockIdx.y, b = blockIdx.z;
    const int q0 = qt * 128;

    const size_t bh = (size_t)(b * Hh + h) * (Tt * HDIM);
    const float* qb = q + bh;
    const float* kb = k + bh;
    const float* vb = v + bh;

    // Q tile (x0.125 is an exact exponent shift on tf32 values)
    #pragma unroll
    for (int i = 0; i < 8; i++) {
        int idx = i * 256 + tid;
        int r = idx >> 4, c4 = (idx & 15) * 4;
        float4 x = *(const float4*)&qb[(size_t)(q0 + r) * HDIM + c4];
        *(float4*)&Qs[r * 68 + c4] = make_float4(x.x * 0.125f, x.y * 0.125f,
                                                 x.z * 0.125f, x.w * 0.125f);
    }

    float mrow[2] = {-1e30f, -1e30f};
    float lrow[2] = {0.f, 0.f};
    float O[8][4];
    #pragma unroll
    for (int nt = 0; nt < 8; nt++)
        #pragma unroll
        for (int j = 0; j < 4; j++) O[nt][j] = 0.f;

    float4 kr[4], vr[4];
    auto LDKV = [&](int k0) {
        #pragma unroll
        for (int i = 0; i < 4; i++) {
            int idx = i * 256 + tid;
            int r = idx >> 4, c4 = (idx & 15) * 4;
            kr[i] = *(const float4*)&kb[(size_t)(k0 + r) * HDIM + c4];
            vr[i] = *(const float4*)&vb[(size_t)(k0 + r) * HDIM + c4];
        }
    };
    auto STKV = [&]() {
        #pragma unroll
        for (int i = 0; i < 4; i++) {
            int idx = i * 256 + tid;
            int r = idx >> 4, c4 = (idx & 15) * 4;
            *(float4*)&Ks[r * 68 + c4] = kr[i];
            *(float4*)&Vs[r * 68 + c4] = vr[i];
        }
    };

    const int ktmax = 2 * qt + 1;
    LDKV(0);

    for (int kt = 0; kt <= ktmax; kt++) {
        const int k0 = kt * 64;
        __syncthreads();
        STKV();
        __syncthreads();
        if (kt < ktmax) LDKV(k0 + 64);

        if (k0 <= q0 + wq + 15) {
            float S[8][4];
            #pragma unroll
            for (int nt = 0; nt < 8; nt++)
                #pragma unroll
                for (int j = 0; j < 4; j++) S[nt][j] = 0.f;

            #pragma unroll
            for (int kk = 0; kk < 64; kk += 8) {
                unsigned a[4];
                a[0] = f2u(Qs[(wq + g    ) * 68 + kk + tg    ]);
                a[1] = f2u(Qs[(wq + g + 8) * 68 + kk + tg    ]);
                a[2] = f2u(Qs[(wq + g    ) * 68 + kk + tg + 4]);
                a[3] = f2u(Qs[(wq + g + 8) * 68 + kk + tg + 4]);
                #pragma unroll
                for (int nt = 0; nt < 8; nt++) {
                    unsigned bb[2];
                    bb[0] = f2u(Ks[(nt * 8 + g) * 68 + kk + tg    ]);
                    bb[1] = f2u(Ks[(nt * 8 + g) * 68 + kk + tg + 4]);
                    mma8(S[nt], a, bb);
                }
            }

            if (k0 + 63 > q0 + wq) {
                int qA = q0 + wq + g, qB = qA + 8;
                #pragma unroll
                for (int nt = 0; nt < 8; nt++) {
                    int c = k0 + nt * 8 + 2 * tg;
                    if (c     > qA) S[nt][0] = -1e30f;
                    if (c + 1 > qA) S[nt][1] = -1e30f;
                    if (c     > qB) S[nt][2] = -1e30f;
                    if (c + 1 > qB) S[nt][3] = -1e30f;
                }
            }

            float mA = -1e30f, mB = -1e30f;
            #pragma unroll
            for (int nt = 0; nt < 8; nt++) {
                mA = fmaxf(mA, fmaxf(S[nt][0], S[nt][1]));
                mB = fmaxf(mB, fmaxf(S[nt][2], S[nt][3]));
            }
            #pragma unroll
            for (int o = 1; o <= 2; o <<= 1) {
                mA = fmaxf(mA, __shfl_xor_sync(0xffffffffu, mA, o));
                mB = fmaxf(mB, __shfl_xor_sync(0xffffffffu, mB, o));
            }
            float nmA = fmaxf(mrow[0], mA), nmB = fmaxf(mrow[1], mB);
            float sA = 0.f, sB = 0.f;
            #pragma unroll
            for (int nt = 0; nt < 8; nt++) {
                S[nt][0] = __expf(S[nt][0] - nmA);
                S[nt][1] = __expf(S[nt][1] - nmA);
                S[nt][2] = __expf(S[nt][2] - nmB);
                S[nt][3] = __expf(S[nt][3] - nmB);
                sA += S[nt][0] + S[nt][1];
                sB += S[nt][2] + S[nt][3];
            }
            #pragma unroll
            for (int o = 1; o <= 2; o <<= 1) {
                sA += __shfl_xor_sync(0xffffffffu, sA, o);
                sB += __shfl_xor_sync(0xffffffffu, sB, o);
            }
            float scA = __expf(mrow[0] - nmA), scB = __expf(mrow[1] - nmB);
            lrow[0] = lrow[0] * scA + sA;  mrow[0] = nmA;
            lrow[1] = lrow[1] * scB + sB;  mrow[1] = nmB;
            #pragma unroll
            for (int nt = 0; nt < 8; nt++) {
                O[nt][0] *= scA; O[nt][1] *= scA;
                O[nt][2] *= scB; O[nt][3] *= scB;
            }

            #pragma unroll
            for (int nt = 0; nt < 8; nt++) {
                int c = nt * 8 + 2 * tg;
                *(float2*)&Ps[(wq + g    ) * 68 + c] = make_float2(rtf(S[nt][0]), rtf(S[nt][1]));
                *(float2*)&Ps[(wq + g + 8) * 68 + c] = make_float2(rtf(S[nt][2]), rtf(S[nt][3]));
            }
            __syncwarp();

            #pragma unroll
            for (int kk = 0; kk < 64; kk += 8) {
                unsigned a[4];
                a[0] = f2u(Ps[(wq + g    ) * 68 + kk + tg    ]);
                a[1] = f2u(Ps[(wq + g + 8) * 68 + kk + tg    ]);
                a[2] = f2u(Ps[(wq + g    ) * 68 + kk + tg + 4]);
                a[3] = f2u(Ps[(wq + g + 8) * 68 + kk + tg + 4]);
                #pragma unroll
                for (int nt = 0; nt < 8; nt++) {
                    unsigned bb[2];
                    bb[0] = f2u(Vs[(kk + tg    ) * 68 + nt * 8 + g]);
                    bb[1] = f2u(Vs[(kk + tg + 4) * 68 + nt * 8 + g]);
                    mma8(O[nt], a, bb);
                }
            }
        }
    }

    // normalize + write rounded ctx [B,T,D] (feeds the Wo GEMM)
    float invA = 1.0f / lrow[0], invB = 1.0f / lrow[1];
    int tA = q0 + wq + g, tB = tA + 8;
    #pragma unroll
    for (int nt = 0; nt < 8; nt++) {
        int c = h * HDIM + nt * 8 + 2 * tg;
        *(float2*)&ctx[((size_t)b * Tt + tA) * Dd + c] =
            make_float2(rtf(O[nt][0] * invA), rtf(O[nt][1] * invA));
        *(float2*)&ctx[((size_t)b * Tt + tB) * Dd + c] =
            make_float2(rtf(O[nt][2] * invB), rtf(O[nt][3] * invB));
    }
}

// ---------------------------------------------------------------------------
extern "C" void kernel_launch(void* const* d_in, const int* in_sizes, int n_in,
                              void* d_out, int out_size)
{
    const float* x  = (const float*)d_in[0];
    const float* Wq = (const float*)d_in[1];
    const float* Wk = (const float*)d_in[2];
    const float* Wv = (const float*)d_in[3];
    const float* Wo = (const float*)d_in[4];
    const float* bo = (const float*)d_in[5];
    float* out = (float*)d_out;

    float *pq, *pk, *pv, *pctx, *pxr, *pwr;
    cudaGetSymbolAddress((void**)&pq,   g_q);
    cudaGetSymbolAddress((void**)&pk,   g_k);
    cudaGetSymbolAddress((void**)&pv,   g_v);
    cudaGetSymbolAddress((void**)&pctx, g_ctx);
    cudaGetSymbolAddress((void**)&pxr,  g_xr);
    cudaGetSymbolAddress((void**)&pwr,  g_wr);
    float* pwq = pwr;
    float* pwk = pwr + (size_t)Dd*Dd;
    float* pwv = pwr + 2*(size_t)Dd*Dd;
    float* pwo = pwr + 3*(size_t)Dd*Dd;

    const int GSMEM = STG * (AS_ST + WS_ST) * (int)sizeof(float);            // 105984
    const int FSMEM = (128*68 + 64*68 + 64*68 + 128*68) * (int)sizeof(float); // 104448
    cudaFuncSetAttribute(gemm_mma,  cudaFuncAttributeMaxDynamicSharedMemorySize, GSMEM);
    cudaFuncSetAttribute(flash_mma, cudaFuncAttributeMaxDynamicSharedMemorySize, FSMEM);

    preround<<<dim3(4096, 5), 256>>>(x, Wq, Wk, Wv, Wo);

    gemm_mma<<<dim3(Dd/128, MTOT/128, 3), 256, GSMEM>>>(
        pxr, pwq, pwk, pwv, pq, pk, pv, nullptr, 1);

    flash_mma<<<dim3(Tt/128, Hh, Bb), 256, FSMEM>>>(pq, pk, pv, pctx);

    gemm_mma<<<dim3(Dd/128, MTOT/128, 1), 256, GSMEM>>>(
        pctx, pwo, nullptr, nullptr, out, nullptr, nullptr, bo, 0);
}

// round 7
// speedup vs baseline: 3.5196x; 1.2462x over previous
#include <cuda_runtime.h>
#include <cstdint>

#define Bb   2
#define Tt   2048
#define Dd   1024
#define Hh   16
#define HDIM 64
#define MTOT (Bb*Tt)        // 4096

// Scratch (allocation-free rule: __device__ globals)
__device__ float g_q[Bb*Hh*Tt*HDIM];
__device__ float g_k[Bb*Hh*Tt*HDIM];
__device__ float g_v[Bb*Hh*Tt*HDIM];
__device__ float g_ctx[Bb*Tt*Dd];
__device__ float g_xr[MTOT*Dd];        // tf32-rounded x
__device__ float g_wr[4][Dd*Dd];       // tf32-rounded Wq,Wk,Wv,Wo

// ---- helpers --------------------------------------------------------------
__device__ __forceinline__ unsigned rtf_u(float x) {
    unsigned u; asm("cvt.rna.tf32.f32 %0, %1;" : "=r"(u) : "f"(x)); return u;
}
__device__ __forceinline__ float rtf(float x) { return __uint_as_float(rtf_u(x)); }
__device__ __forceinline__ unsigned f2u(float x) { return __float_as_uint(x); }
__device__ __forceinline__ float4 cvt4(float4 v) {
    return make_float4(rtf(v.x), rtf(v.y), rtf(v.z), rtf(v.w));
}
__device__ __forceinline__ void cpa16(void* dst, const void* src) {
    unsigned s = (unsigned)__cvta_generic_to_shared(dst);
    asm volatile("cp.async.cg.shared.global [%0], [%1], 16;\n" :: "r"(s), "l"(src));
}
__device__ __forceinline__ float ex2(float x) {
    float y; asm("ex2.approx.ftz.f32 %0, %1;" : "=f"(y) : "f"(x)); return y;
}
// mma.sync m16n8k8 tf32: D += A*B
// A: a0=(g,tg) a1=(g+8,tg) a2=(g,tg+4) a3=(g+8,tg+4)
// B: b0=(k=tg,n=g) b1=(k=tg+4,n=g)
// C: c0=(g,2tg) c1=(g,2tg+1) c2=(g+8,2tg) c3=(g+8,2tg+1)
__device__ __forceinline__ void mma8(float* d, const unsigned* a, const unsigned* b) {
    asm volatile(
        "mma.sync.aligned.m16n8k8.row.col.f32.tf32.tf32.f32 "
        "{%0,%1,%2,%3}, {%4,%5,%6,%7}, {%8,%9}, {%0,%1,%2,%3};\n"
        : "+f"(d[0]), "+f"(d[1]), "+f"(d[2]), "+f"(d[3])
        : "r"(a[0]), "r"(a[1]), "r"(a[2]), "r"(a[3]), "r"(b[0]), "r"(b[1]));
}

// ---------------------------------------------------------------------------
// Pre-round x and the 4 weight matrices to tf32 values (kept in fp32).
// ---------------------------------------------------------------------------
__global__ void preround(const float* __restrict__ x,  const float* __restrict__ wq,
                         const float* __restrict__ wk, const float* __restrict__ wv,
                         const float* __restrict__ wo)
{
    int z = blockIdx.y;
    const float* s; float* d; int n;
    if (z == 0) { s = x;  d = g_xr;    n = MTOT*Dd; }
    else {
        s = (z == 1) ? wq : (z == 2) ? wk : (z == 3) ? wv : wo;
        d = g_wr[z-1]; n = Dd*Dd;
    }
    int i = (blockIdx.x * blockDim.x + threadIdx.x) * 4;
    if (i < n) *(float4*)&d[i] = cvt4(*(const float4*)&s[i]);
}

// ---------------------------------------------------------------------------
// GEMM (tf32 mma.sync, 3-stage cp.async, ONE sync per K-block):
// C[128x128] = A[M,1024]*W[1024,1024] (+bias).  8 warps (2m x 4n), warp 64x32.
// A stride 36 (banks 4g+tg), W stride 136 (banks 8tg+g) -> conflict-free.
// mode 0: row-major + bias.  mode 1: head-split + rtf, z selects Q/K/V.
// ---------------------------------------------------------------------------
#define AS_ST (128*36)
#define WS_ST (32*136)
#define GSTG  3
#define GSMEM (GSTG * (AS_ST + WS_ST) * 4)     // 107520 B

__global__ __launch_bounds__(256, 2)
void gemm_mma(const float* __restrict__ A,
              const float* __restrict__ W0, const float* __restrict__ W1,
              const float* __restrict__ W2,
              float* __restrict__ C0, float* __restrict__ C1,
              float* __restrict__ C2,
              const float* __restrict__ bias, int mode)
{
    extern __shared__ float sh[];
    float* Apool = sh;                  // [GSTG][128][36]
    float* Wpool = sh + GSTG * AS_ST;   // [GSTG][32][136]

    const float* W = (blockIdx.z == 0) ? W0 : (blockIdx.z == 1) ? W1 : W2;
    float*       C = (blockIdx.z == 0) ? C0 : (blockIdx.z == 1) ? C1 : C2;

    const int tid = threadIdx.x;
    const int lane = tid & 31, warp = tid >> 5;
    const int g = lane >> 2, tg = lane & 3;
    const int wm = warp >> 2;       // 0..1  (64 rows)
    const int wn = warp & 3;        // 0..3  (32 cols)
    const int m0 = blockIdx.y * 128;
    const int n0 = blockIdx.x * 128;

    float acc[4][4][4];
    #pragma unroll
    for (int mt = 0; mt < 4; mt++)
        #pragma unroll
        for (int nt = 0; nt < 4; nt++)
            #pragma unroll
            for (int c = 0; c < 4; c++) acc[mt][nt][c] = 0.f;

    auto ISSUE = [&](int it) {
        const int k0 = it * 32;
        float* Ab = Apool + (it % GSTG) * AS_ST;
        float* Wb = Wpool + (it % GSTG) * WS_ST;
        #pragma unroll
        for (int j = 0; j < 4; j++) {          // A: 128 rows x 32 floats
            int id = j * 256 + tid;
            int r = id >> 3, c = id & 7;
            cpa16(&Ab[r * 36 + c * 4], &A[(size_t)(m0 + r) * 1024 + k0 + c * 4]);
        }
        #pragma unroll
        for (int j = 0; j < 4; j++) {          // W: 32 rows x 128 floats
            int id = j * 256 + tid;
            int r = id >> 5, c = id & 31;
            cpa16(&Wb[r * 136 + c * 4], &W[(size_t)(k0 + r) * 1024 + n0 + c * 4]);
        }
    };

    ISSUE(0); asm volatile("cp.async.commit_group;\n");
    ISSUE(1); asm volatile("cp.async.commit_group;\n");

    for (int it = 0; it < 32; it++) {
        asm volatile("cp.async.wait_group 1;\n");  // stage `it` copied (this thread)
        __syncthreads();                           // all threads' copies + prior compute done
        if (it + 2 < 32) ISSUE(it + 2);            // WAR-safe: stage (it+2)%3 == (it-1)%3
        asm volatile("cp.async.commit_group;\n");  // always commit (keeps group count)

        const float* Ab = Apool + (it % GSTG) * AS_ST;
        const float* Wb = Wpool + (it % GSTG) * WS_ST;
        #pragma unroll
        for (int kk = 0; kk < 32; kk += 8) {
            unsigned a[4][4], b[4][2];
            #pragma unroll
            for (int mt = 0; mt < 4; mt++) {
                int rb = wm * 64 + mt * 16;
                a[mt][0] = f2u(Ab[(rb + g    ) * 36 + kk + tg    ]);
                a[mt][1] = f2u(Ab[(rb + g + 8) * 36 + kk + tg    ]);
                a[mt][2] = f2u(Ab[(rb + g    ) * 36 + kk + tg + 4]);
                a[mt][3] = f2u(Ab[(rb + g + 8) * 36 + kk + tg + 4]);
            }
            #pragma unroll
            for (int nt = 0; nt < 4; nt++) {
                int nb = wn * 32 + nt * 8;
                b[nt][0] = f2u(Wb[(kk + tg    ) * 136 + nb + g]);
                b[nt][1] = f2u(Wb[(kk + tg + 4) * 136 + nb + g]);
            }
            #pragma unroll
            for (int mt = 0; mt < 4; mt++)
                #pragma unroll
                for (int nt = 0; nt < 4; nt++)
                    mma8(acc[mt][nt], a[mt], b[nt]);
        }
    }

    // Epilogue
    #pragma unroll
    for (int mt = 0; mt < 4; mt++) {
        #pragma unroll
        for (int nt = 0; nt < 4; nt++) {
            int colL = wn * 32 + nt * 8 + 2 * tg;
            int rA = m0 + wm * 64 + mt * 16 + g;
            int rB = rA + 8;
            float c0 = acc[mt][nt][0], c1 = acc[mt][nt][1];
            float c2 = acc[mt][nt][2], c3 = acc[mt][nt][3];
            if (mode == 0) {
                float b0 = bias[n0 + colL], b1 = bias[n0 + colL + 1];
                *(float2*)&C[(size_t)rA * 1024 + n0 + colL] = make_float2(c0 + b0, c1 + b1);
                *(float2*)&C[(size_t)rB * 1024 + n0 + colL] = make_float2(c2 + b0, c3 + b1);
            } else {
                int gc = n0 + colL;
                int h = gc >> 6, d = gc & 63;
                int bA = rA >> 11, tA = rA & 2047;
                int bB = rB >> 11, tB = rB & 2047;
                size_t baseA = (size_t)bA * (Hh*Tt*HDIM) + (size_t)h * (Tt*HDIM)
                             + (size_t)tA * HDIM + d;
                size_t baseB = (size_t)bB * (Hh*Tt*HDIM) + (size_t)h * (Tt*HDIM)
                             + (size_t)tB * HDIM + d;
                *(float2*)&C[baseA] = make_float2(rtf(c0), rtf(c1));
                *(float2*)&C[baseB] = make_float2(rtf(c2), rtf(c3));
            }
        }
    }
}

// ---------------------------------------------------------------------------
// Flash attention (tf32 mma.sync): block = 128 queries of one (b,h),
// 8 warps x 16 q-rows.  Double-buffered K/V via cp.async, ONE sync per tile.
// P: S-fragment -> A-fragment via warp shuffles (no smem round trip).
// Softmax in exp2 domain (log2e folded into Q scale).
// smem: Qs[128][68] | Ks[2][64][68] | Vs[2][64][72] = 106496 B, 2 CTAs/SM.
// ---------------------------------------------------------------------------
#define FSMEM ((128*68 + 2*64*68 + 2*64*72) * 4)

__global__ __launch_bounds__(256, 2)
void flash_mma(const float* __restrict__ q, const float* __restrict__ k,
               const float* __restrict__ v, float* __restrict__ ctx)
{
    extern __shared__ float sm[];
    float* Qs = sm;                   // [128][68]
    float* Ks = sm + 128 * 68;        // [2][64][68]
    float* Vs = Ks + 2 * 64 * 68;     // [2][64][72]

    const int tid  = threadIdx.x;
    const int lane = tid & 31, warp = tid >> 5;
    const int g = lane >> 2, tg = lane & 3;
    const int wq = warp * 16;
    const int qt = (gridDim.x - 1) - blockIdx.x;      // heavy blocks first
    const int h = blockIdx.y, b = blockIdx.z;
    const int q0 = qt * 128;

    const size_t bh = (size_t)(b * Hh + h) * (Tt * HDIM);
    const float* qb = q + bh;
    const float* kb = k + bh;
    const float* vb = v + bh;

    // Q tile: scale by (1/sqrt(64)) * log2(e), tf32-rounded
    const float QSC = 0.18033688011112042f;
    #pragma unroll
    for (int i = 0; i < 8; i++) {
        int idx = i * 256 + tid;
        int r = idx >> 4, c4 = (idx & 15) * 4;
        float4 x = *(const float4*)&qb[(size_t)(q0 + r) * HDIM + c4];
        *(float4*)&Qs[r * 68 + c4] = make_float4(rtf(x.x * QSC), rtf(x.y * QSC),
                                                 rtf(x.z * QSC), rtf(x.w * QSC));
    }

    auto ISSKV = [&](int kt, int s) {
        const int k0 = kt * 64;
        #pragma unroll
        for (int i = 0; i < 4; i++) {
            int id = i * 256 + tid;
            int r = id >> 4, c4 = (id & 15) * 4;
            cpa16(&Ks[s * (64*68) + r * 68 + c4], &kb[(size_t)(k0 + r) * HDIM + c4]);
            cpa16(&Vs[s * (64*72) + r * 72 + c4], &vb[(size_t)(k0 + r) * HDIM + c4]);
        }
    };

    float mrow[2] = {-1e30f, -1e30f};
    float lrow[2] = {0.f, 0.f};
    float O[8][4];
    #pragma unroll
    for (int nt = 0; nt < 8; nt++)
        #pragma unroll
        for (int j = 0; j < 4; j++) O[nt][j] = 0.f;

    const int ktmax = 2 * qt + 1;
    ISSKV(0, 0); asm volatile("cp.async.commit_group;\n");

    for (int kt = 0; kt <= ktmax; kt++) {
        const int s = kt & 1;
        const int k0 = kt * 64;
        asm volatile("cp.async.wait_group 0;\n");   // tile kt copied (this thread)
        __syncthreads();                            // all copies visible; prior compute done
        if (kt < ktmax) ISSKV(kt + 1, s ^ 1);       // WAR-safe after the barrier
        asm volatile("cp.async.commit_group;\n");

        if (k0 <= q0 + wq + 15) {                   // warp has unmasked rows
            const float* Kb = Ks + s * (64*68);
            const float* Vb = Vs + s * (64*72);

            // S = Q K^T  (16 x 64, log2 domain)
            float S[8][4];
            #pragma unroll
            for (int nt = 0; nt < 8; nt++)
                #pragma unroll
                for (int j = 0; j < 4; j++) S[nt][j] = 0.f;

            #pragma unroll
            for (int kk = 0; kk < 64; kk += 8) {
                unsigned a[4];
                a[0] = f2u(Qs[(wq + g    ) * 68 + kk + tg    ]);
                a[1] = f2u(Qs[(wq + g + 8) * 68 + kk + tg    ]);
                a[2] = f2u(Qs[(wq + g    ) * 68 + kk + tg + 4]);
                a[3] = f2u(Qs[(wq + g + 8) * 68 + kk + tg + 4]);
                #pragma unroll
                for (int nt = 0; nt < 8; nt++) {
                    unsigned bv[2];
                    bv[0] = f2u(Kb[(nt * 8 + g) * 68 + kk + tg    ]);
                    bv[1] = f2u(Kb[(nt * 8 + g) * 68 + kk + tg + 4]);
                    mma8(S[nt], a, bv);
                }
            }

            if (k0 + 63 > q0 + wq) {                // diagonal tile mask
                int qA = q0 + wq + g, qB = qA + 8;
                #pragma unroll
                for (int nt = 0; nt < 8; nt++) {
                    int c = k0 + nt * 8 + 2 * tg;
                    if (c     > qA) S[nt][0] = -1e30f;
                    if (c + 1 > qA) S[nt][1] = -1e30f;
                    if (c     > qB) S[nt][2] = -1e30f;
                    if (c + 1 > qB) S[nt][3] = -1e30f;
                }
            }

            // online softmax, exp2 domain (rows g, g+8)
            float mA = -1e30f, mB = -1e30f;
            #pragma unroll
            for (int nt = 0; nt < 8; nt++) {
                mA = fmaxf(mA, fmaxf(S[nt][0], S[nt][1]));
                mB = fmaxf(mB, fmaxf(S[nt][2], S[nt][3]));
            }
            #pragma unroll
            for (int o = 1; o <= 2; o <<= 1) {
                mA = fmaxf(mA, __shfl_xor_sync(0xffffffffu, mA, o));
                mB = fmaxf(mB, __shfl_xor_sync(0xffffffffu, mB, o));
            }
            float nmA = fmaxf(mrow[0], mA), nmB = fmaxf(mrow[1], mB);
            float sA = 0.f, sB = 0.f;
            #pragma unroll
            for (int nt = 0; nt < 8; nt++) {
                S[nt][0] = ex2(S[nt][0] - nmA);
                S[nt][1] = ex2(S[nt][1] - nmA);
                S[nt][2] = ex2(S[nt][2] - nmB);
                S[nt][3] = ex2(S[nt][3] - nmB);
                sA += S[nt][0] + S[nt][1];
                sB += S[nt][2] + S[nt][3];
            }
            #pragma unroll
            for (int o = 1; o <= 2; o <<= 1) {
                sA += __shfl_xor_sync(0xffffffffu, sA, o);
                sB += __shfl_xor_sync(0xffffffffu, sB, o);
            }
            float scA = ex2(mrow[0] - nmA), scB = ex2(mrow[1] - nmB);
            lrow[0] = lrow[0] * scA + sA;  mrow[0] = nmA;
            lrow[1] = lrow[1] * scB + sB;  mrow[1] = nmB;
            #pragma unroll
            for (int nt = 0; nt < 8; nt++) {
                O[nt][0] *= scA; O[nt][1] *= scA;
                O[nt][2] *= scB; O[nt][3] *= scB;
            }

            // O += P V : repack S C-frags to A-frags via shuffles, mma
            const int src0 = (lane & ~3) | (tg >> 1);   // holds cols {2*(tg>>1), +1}
            const int src1 = src0 + 2;                  // holds cols {tg+4 pair}
            const bool odd = tg & 1;
            #pragma unroll
            for (int j = 0; j < 8; j++) {
                float v00 = __shfl_sync(0xffffffffu, S[j][0], src0);
                float v01 = __shfl_sync(0xffffffffu, S[j][1], src0);
                float v02 = __shfl_sync(0xffffffffu, S[j][2], src0);
                float v03 = __shfl_sync(0xffffffffu, S[j][3], src0);
                float v10 = __shfl_sync(0xffffffffu, S[j][0], src1);
                float v11 = __shfl_sync(0xffffffffu, S[j][1], src1);
                float v12 = __shfl_sync(0xffffffffu, S[j][2], src1);
                float v13 = __shfl_sync(0xffffffffu, S[j][3], src1);
                unsigned a[4];
                a[0] = rtf_u(odd ? v01 : v00);   // P(g,    8j+tg)
                a[1] = rtf_u(odd ? v03 : v02);   // P(g+8,  8j+tg)
                a[2] = rtf_u(odd ? v11 : v10);   // P(g,    8j+tg+4)
                a[3] = rtf_u(odd ? v13 : v12);   // P(g+8,  8j+tg+4)
                #pragma unroll
                for (int nt = 0; nt < 8; nt++) {
                    unsigned bv[2];
                    bv[0] = f2u(Vb[(j * 8 + tg    ) * 72 + nt * 8 + g]);
                    bv[1] = f2u(Vb[(j * 8 + tg + 4) * 72 + nt * 8 + g]);
                    mma8(O[nt], a, bv);
                }
            }
        }
    }

    // normalize + write rounded ctx [B,T,D] (feeds the Wo GEMM)
    float invA = 1.0f / lrow[0], invB = 1.0f / lrow[1];
    int tA = q0 + wq + g, tB = tA + 8;
    #pragma unroll
    for (int nt = 0; nt < 8; nt++) {
        int c = h * HDIM + nt * 8 + 2 * tg;
        *(float2*)&ctx[((size_t)b * Tt + tA) * Dd + c] =
            make_float2(rtf(O[nt][0] * invA), rtf(O[nt][1] * invA));
        *(float2*)&ctx[((size_t)b * Tt + tB) * Dd + c] =
            make_float2(rtf(O[nt][2] * invB), rtf(O[nt][3] * invB));
    }
}

// ---------------------------------------------------------------------------
extern "C" void kernel_launch(void* const* d_in, const int* in_sizes, int n_in,
                              void* d_out, int out_size)
{
    const float* x  = (const float*)d_in[0];
    const float* Wq = (const float*)d_in[1];
    const float* Wk = (const float*)d_in[2];
    const float* Wv = (const float*)d_in[3];
    const float* Wo = (const float*)d_in[4];
    const float* bo = (const float*)d_in[5];
    float* out = (float*)d_out;

    float *pq, *pk, *pv, *pctx, *pxr, *pwr;
    cudaGetSymbolAddress((void**)&pq,   g_q);
    cudaGetSymbolAddress((void**)&pk,   g_k);
    cudaGetSymbolAddress((void**)&pv,   g_v);
    cudaGetSymbolAddress((void**)&pctx, g_ctx);
    cudaGetSymbolAddress((void**)&pxr,  g_xr);
    cudaGetSymbolAddress((void**)&pwr,  g_wr);
    float* pwq = pwr;
    float* pwk = pwr + (size_t)Dd*Dd;
    float* pwv = pwr + 2*(size_t)Dd*Dd;
    float* pwo = pwr + 3*(size_t)Dd*Dd;

    cudaFuncSetAttribute(gemm_mma,  cudaFuncAttributeMaxDynamicSharedMemorySize, GSMEM);
    cudaFuncSetAttribute(flash_mma, cudaFuncAttributeMaxDynamicSharedMemorySize, FSMEM);

    preround<<<dim3(4096, 5), 256>>>(x, Wq, Wk, Wv, Wo);

    gemm_mma<<<dim3(Dd/128, MTOT/128, 3), 256, GSMEM>>>(
        pxr, pwq, pwk, pwv, pq, pk, pv, nullptr, 1);

    flash_mma<<<dim3(Tt/128, Hh, Bb), 256, FSMEM>>>(pq, pk, pv, pctx);

    gemm_mma<<<dim3(Dd/128, MTOT/128, 1), 256, GSMEM>>>(
        pctx, pwo, nullptr, nullptr, out, nullptr, nullptr, bo, 0);
}

// round 8
// speedup vs baseline: 3.7044x; 1.0525x over previous
#include <cuda_runtime.h>
#include <cstdint>

#define Bb   2
#define Tt   2048
#define Dd   1024
#define Hh   16
#define HDIM 64
#define MTOT (Bb*Tt)        // 4096

// Scratch (allocation-free rule: __device__ globals)
__device__ float g_q[Bb*Hh*Tt*HDIM];     // d-dim permuted
__device__ float g_k[Bb*Hh*Tt*HDIM];     // d-dim permuted
__device__ float g_v[Bb*Hh*Tt*HDIM];     // unpermuted
__device__ float g_ctx[Bb*Tt*Dd];        // d-dim permuted (A of Wo gemm)
__device__ float g_xr[MTOT*Dd];          // tf32-rounded x, k-perm
__device__ float g_wt[4][Dd*Dd];         // tf32-rounded W^T [n][k], k-perm

// ---- helpers --------------------------------------------------------------
__device__ __forceinline__ unsigned rtf_u(float x) {
    unsigned u; asm("cvt.rna.tf32.f32 %0, %1;" : "=r"(u) : "f"(x)); return u;
}
__device__ __forceinline__ float rtf(float x) { return __uint_as_float(rtf_u(x)); }
__device__ __forceinline__ unsigned f2u(float x) { return __float_as_uint(x); }
__device__ __forceinline__ void cpa16(void* dst, const void* src) {
    unsigned s = (unsigned)__cvta_generic_to_shared(dst);
    asm volatile("cp.async.cg.shared.global [%0], [%1], 16;\n" :: "r"(s), "l"(src));
}
__device__ __forceinline__ float ex2(float x) {
    float y; asm("ex2.approx.ftz.f32 %0, %1;" : "=f"(y) : "f"(x)); return y;
}
// position p holds original k-offset (p>>1)+4*(p&1)  (within each 8-block)
__device__ __forceinline__ int korig(int p) {
    return (p & ~7) + (((p & 7) >> 1)) + 4 * (p & 1);
}
// original offset c stored at position 2*(c&3)+((c>>2)&1)
__device__ __forceinline__ int kpos(int c) {
    return (c & ~7) + 2 * (c & 3) + ((c >> 2) & 1);
}
// mma.sync m16n8k8 tf32: D += A*B
// A: a0=(g,tg) a1=(g+8,tg) a2=(g,tg+4) a3=(g+8,tg+4)
// B: b0=(k=tg,n=g) b1=(k=tg+4,n=g)
// C: c0=(g,2tg) c1=(g,2tg+1) c2=(g+8,2tg) c3=(g+8,2tg+1)
__device__ __forceinline__ void mma8(float* d, const unsigned* a, const unsigned* b) {
    asm volatile(
        "mma.sync.aligned.m16n8k8.row.col.f32.tf32.tf32.f32 "
        "{%0,%1,%2,%3}, {%4,%5,%6,%7}, {%8,%9}, {%0,%1,%2,%3};\n"
        : "+f"(d[0]), "+f"(d[1]), "+f"(d[2]), "+f"(d[3])
        : "r"(a[0]), "r"(a[1]), "r"(a[2]), "r"(a[3]), "r"(b[0]), "r"(b[1]));
}

// ---------------------------------------------------------------------------
// preround_x: g_xr[m][p] = rtf(x[m][korig(p)])
// ---------------------------------------------------------------------------
__global__ void preround_x(const float* __restrict__ x) {
    int i = (blockIdx.x * 256 + threadIdx.x) * 4;
    int m = i >> 10, kp = i & 1023;
    const float* row = x + (size_t)m * 1024;
    float4 o;
    o.x = rtf(row[korig(kp)]);
    o.y = rtf(row[korig(kp + 1)]);
    o.z = rtf(row[korig(kp + 2)]);
    o.w = rtf(row[korig(kp + 3)]);
    *(float4*)&g_xr[i] = o;
}

// ---------------------------------------------------------------------------
// transW: g_wt[z][n][p] = rtf(W_z[k0+korig(p)][n])  (transpose + k-perm)
// ---------------------------------------------------------------------------
__global__ void transW(const float* __restrict__ wq, const float* __restrict__ wk,
                       const float* __restrict__ wv, const float* __restrict__ wo)
{
    __shared__ float t[32][33];
    int z = blockIdx.z;
    const float* W = (z == 0) ? wq : (z == 1) ? wk : (z == 2) ? wv : wo;
    float* D = g_wt[z];
    int k0 = blockIdx.x * 32, n0 = blockIdx.y * 32;
    int tx = threadIdx.x, ty = threadIdx.y;
    #pragma unroll
    for (int i = 0; i < 32; i += 8)
        t[ty + i][tx] = rtf(W[(size_t)(k0 + ty + i) * 1024 + n0 + tx]);
    __syncthreads();
    int src = korig(tx);
    #pragma unroll
    for (int i = 0; i < 32; i += 8)
        D[(size_t)(n0 + ty + i) * 1024 + k0 + tx] = t[src][ty + i];
}

// ---------------------------------------------------------------------------
// GEMM (tf32 mma.sync, float2 fragment loads, 2-stage cp.async):
// C[128x128] = A[M,1024] * Wt[N,1024]^T (+bias).  8 warps (2m x 4n), warp 64x32.
// A,Wt k-permuted -> frag k-pairs adjacent -> LDS.64.  Strides 40 (8r+2tg banks).
// mode 0: row-major + bias.  mode 1: head-split, z:{Q,K}-> d-permuted, V plain.
// ---------------------------------------------------------------------------
#define AS_ST (128*40)
#define WS_ST (128*40)
#define GSTG  2
#define GSMEM (GSTG * (AS_ST + WS_ST) * 4)     // 81920 B

__global__ __launch_bounds__(256, 2)
void gemm_mma(const float* __restrict__ A,
              const float* __restrict__ W0, const float* __restrict__ W1,
              const float* __restrict__ W2,
              float* __restrict__ C0, float* __restrict__ C1,
              float* __restrict__ C2,
              const float* __restrict__ bias, int mode)
{
    extern __shared__ float sh[];
    float* Apool = sh;                  // [2][128][40]
    float* Wpool = sh + GSTG * AS_ST;   // [2][128][40]  ([n][k] layout)

    const float* W = (blockIdx.z == 0) ? W0 : (blockIdx.z == 1) ? W1 : W2;
    float*       C = (blockIdx.z == 0) ? C0 : (blockIdx.z == 1) ? C1 : C2;

    const int tid = threadIdx.x;
    const int lane = tid & 31, warp = tid >> 5;
    const int g = lane >> 2, tg = lane & 3;
    const int wm = warp >> 2;       // 0..1  (64 rows)
    const int wn = warp & 3;        // 0..3  (32 cols)
    const int m0 = blockIdx.y * 128;
    const int n0 = blockIdx.x * 128;

    float acc[4][4][4];
    #pragma unroll
    for (int mt = 0; mt < 4; mt++)
        #pragma unroll
        for (int nt = 0; nt < 4; nt++)
            #pragma unroll
            for (int c = 0; c < 4; c++) acc[mt][nt][c] = 0.f;

    auto ISSUE = [&](int it) {
        const int k0 = it * 32;
        float* Ab = Apool + (it & 1) * AS_ST;
        float* Wb = Wpool + (it & 1) * WS_ST;
        #pragma unroll
        for (int j = 0; j < 4; j++) {          // A: 128 rows x 32 floats
            int id = j * 256 + tid;
            int r = id >> 3, c = id & 7;
            cpa16(&Ab[r * 40 + c * 4], &A[(size_t)(m0 + r) * 1024 + k0 + c * 4]);
        }
        #pragma unroll
        for (int j = 0; j < 4; j++) {          // Wt: 128 rows (n) x 32 floats (k)
            int id = j * 256 + tid;
            int r = id >> 3, c = id & 7;
            cpa16(&Wb[r * 40 + c * 4], &W[(size_t)(n0 + r) * 1024 + k0 + c * 4]);
        }
    };

    ISSUE(0); asm volatile("cp.async.commit_group;\n");

    for (int it = 0; it < 32; it++) {
        asm volatile("cp.async.wait_group 0;\n");  // stage `it` copied (this thread)
        __syncthreads();                           // all copies visible; prior compute done
        if (it + 1 < 32) {                         // WAR-safe: writes stage (it-1)&1
            ISSUE(it + 1);
            asm volatile("cp.async.commit_group;\n");
        }

        const float* Ab = Apool + (it & 1) * AS_ST;
        const float* Wb = Wpool + (it & 1) * WS_ST;
        #pragma unroll
        for (int kk = 0; kk < 32; kk += 8) {
            unsigned a[4][4], b[4][2];
            #pragma unroll
            for (int mt = 0; mt < 4; mt++) {
                int rb = wm * 64 + mt * 16;
                float2 lo = *(const float2*)&Ab[(rb + g    ) * 40 + kk + 2 * tg];
                float2 hi = *(const float2*)&Ab[(rb + g + 8) * 40 + kk + 2 * tg];
                a[mt][0] = f2u(lo.x); a[mt][1] = f2u(hi.x);
                a[mt][2] = f2u(lo.y); a[mt][3] = f2u(hi.y);
            }
            #pragma unroll
            for (int nt = 0; nt < 4; nt++) {
                int nb = wn * 32 + nt * 8;
                float2 bp = *(const float2*)&Wb[(nb + g) * 40 + kk + 2 * tg];
                b[nt][0] = f2u(bp.x); b[nt][1] = f2u(bp.y);
            }
            #pragma unroll
            for (int mt = 0; mt < 4; mt++)
                #pragma unroll
                for (int nt = 0; nt < 4; nt++)
                    mma8(acc[mt][nt], a[mt], b[nt]);
        }
    }

    // Epilogue
    const bool permD = (mode == 1) && (blockIdx.z < 2);   // Q,K: permute d
    #pragma unroll
    for (int mt = 0; mt < 4; mt++) {
        #pragma unroll
        for (int nt = 0; nt < 4; nt++) {
            int colL = wn * 32 + nt * 8 + 2 * tg;
            int rA = m0 + wm * 64 + mt * 16 + g;
            int rB = rA + 8;
            float c0 = acc[mt][nt][0], c1 = acc[mt][nt][1];
            float c2 = acc[mt][nt][2], c3 = acc[mt][nt][3];
            if (mode == 0) {
                float b0 = bias[n0 + colL], b1 = bias[n0 + colL + 1];
                *(float2*)&C[(size_t)rA * 1024 + n0 + colL] = make_float2(c0 + b0, c1 + b1);
                *(float2*)&C[(size_t)rB * 1024 + n0 + colL] = make_float2(c2 + b0, c3 + b1);
            } else {
                int gc = n0 + colL;
                int h = gc >> 6, d = gc & 63;
                int bA = rA >> 11, tA = rA & 2047;
                int bB = rB >> 11, tB = rB & 2047;
                float* dA = &C[((size_t)(bA * Hh + h) * Tt + tA) * HDIM];
                float* dB = &C[((size_t)(bB * Hh + h) * Tt + tB) * HDIM];
                if (permD) {
                    int p0 = kpos(d), p1 = kpos(d + 1);
                    dA[p0] = rtf(c0); dA[p1] = rtf(c1);
                    dB[p0] = rtf(c2); dB[p1] = rtf(c3);
                } else {
                    *(float2*)&dA[d] = make_float2(rtf(c0), rtf(c1));
                    *(float2*)&dB[d] = make_float2(rtf(c2), rtf(c3));
                }
            }
        }
    }
}

// ---------------------------------------------------------------------------
// Flash attention (tf32 mma.sync): block = 128 queries of one (b,h),
// 8 warps x 16 q-rows.  Q/K d-permuted -> frag loads LDS.64.  V plain.
// Double-buffered K/V via cp.async, ONE sync per tile.  P via shuffles.
// exp2-domain softmax.  smem: Qs[128][72] | Ks[2][64][72] | Vs[2][64][72].
// ctx written d-permuted (feeds Wo gemm A operand).
// ---------------------------------------------------------------------------
#define FSMEM ((128*72 + 2*64*72 + 2*64*72) * 4)   // 110592 B

__global__ __launch_bounds__(256, 2)
void flash_mma(const float* __restrict__ q, const float* __restrict__ k,
               const float* __restrict__ v, float* __restrict__ ctx)
{
    extern __shared__ float sm[];
    float* Qs = sm;                   // [128][72]
    float* Ks = sm + 128 * 72;        // [2][64][72]
    float* Vs = Ks + 2 * 64 * 72;     // [2][64][72]

    const int tid  = threadIdx.x;
    const int lane = tid & 31, warp = tid >> 5;
    const int g = lane >> 2, tg = lane & 3;
    const int wq = warp * 16;
    const int qt = (gridDim.x - 1) - blockIdx.x;      // heavy blocks first
    const int h = blockIdx.y, b = blockIdx.z;
    const int q0 = qt * 128;

    const size_t bh = (size_t)(b * Hh + h) * (Tt * HDIM);
    const float* qb = q + bh;
    const float* kb = k + bh;
    const float* vb = v + bh;

    // Q tile: scale by (1/sqrt(64))*log2(e), re-rounded to tf32
    const float QSC = 0.18033688011112042f;
    #pragma unroll
    for (int i = 0; i < 8; i++) {
        int idx = i * 256 + tid;
        int r = idx >> 4, c4 = (idx & 15) * 4;
        float4 x = *(const float4*)&qb[(size_t)(q0 + r) * HDIM + c4];
        *(float4*)&Qs[r * 72 + c4] = make_float4(rtf(x.x * QSC), rtf(x.y * QSC),
                                                 rtf(x.z * QSC), rtf(x.w * QSC));
    }

    auto ISSKV = [&](int kt, int s) {
        const int k0 = kt * 64;
        #pragma unroll
        for (int i = 0; i < 4; i++) {
            int id = i * 256 + tid;
            int r = id >> 4, c4 = (id & 15) * 4;
            cpa16(&Ks[s * (64*72) + r * 72 + c4], &kb[(size_t)(k0 + r) * HDIM + c4]);
            cpa16(&Vs[s * (64*72) + r * 72 + c4], &vb[(size_t)(k0 + r) * HDIM + c4]);
        }
    };

    float mrow[2] = {-1e30f, -1e30f};
    float lrow[2] = {0.f, 0.f};
    float O[8][4];
    #pragma unroll
    for (int nt = 0; nt < 8; nt++)
        #pragma unroll
        for (int j = 0; j < 4; j++) O[nt][j] = 0.f;

    const int ktmax = 2 * qt + 1;
    ISSKV(0, 0); asm volatile("cp.async.commit_group;\n");

    for (int kt = 0; kt <= ktmax; kt++) {
        const int s = kt & 1;
        const int k0 = kt * 64;
        asm volatile("cp.async.wait_group 0;\n");
        __syncthreads();
        if (kt < ktmax) {
            ISSKV(kt + 1, s ^ 1);
            asm volatile("cp.async.commit_group;\n");
        }

        if (k0 <= q0 + wq + 15) {                   // warp has unmasked rows
            const float* Kb = Ks + s * (64*72);
            const float* Vb = Vs + s * (64*72);

            // S = Q K^T  (16 x 64, log2 domain)
            float S[8][4];
            #pragma unroll
            for (int nt = 0; nt < 8; nt++)
                #pragma unroll
                for (int j = 0; j < 4; j++) S[nt][j] = 0.f;

            #pragma unroll
            for (int kk = 0; kk < 64; kk += 8) {
                float2 qlo = *(const float2*)&Qs[(wq + g    ) * 72 + kk + 2 * tg];
                float2 qhi = *(const float2*)&Qs[(wq + g + 8) * 72 + kk + 2 * tg];
                unsigned a[4] = { f2u(qlo.x), f2u(qhi.x), f2u(qlo.y), f2u(qhi.y) };
                #pragma unroll
                for (int nt = 0; nt < 8; nt++) {
                    float2 kp = *(const float2*)&Kb[(nt * 8 + g) * 72 + kk + 2 * tg];
                    unsigned bv[2] = { f2u(kp.x), f2u(kp.y) };
                    mma8(S[nt], a, bv);
                }
            }

            if (k0 + 63 > q0 + wq) {                // diagonal tile mask
                int qA = q0 + wq + g, qB = qA + 8;
                #pragma unroll
                for (int nt = 0; nt < 8; nt++) {
                    int c = k0 + nt * 8 + 2 * tg;
                    if (c     > qA) S[nt][0] = -1e30f;
                    if (c + 1 > qA) S[nt][1] = -1e30f;
                    if (c     > qB) S[nt][2] = -1e30f;
                    if (c + 1 > qB) S[nt][3] = -1e30f;
                }
            }

            // online softmax, exp2 domain (rows g, g+8)
            float mA = -1e30f, mB = -1e30f;
            #pragma unroll
            for (int nt = 0; nt < 8; nt++) {
                mA = fmaxf(mA, fmaxf(S[nt][0], S[nt][1]));
                mB = fmaxf(mB, fmaxf(S[nt][2], S[nt][3]));
            }
            #pragma unroll
            for (int o = 1; o <= 2; o <<= 1) {
                mA = fmaxf(mA, __shfl_xor_sync(0xffffffffu, mA, o));
                mB = fmaxf(mB, __shfl_xor_sync(0xffffffffu, mB, o));
            }
            float nmA = fmaxf(mrow[0], mA), nmB = fmaxf(mrow[1], mB);
            float sA = 0.f, sB = 0.f;
            #pragma unroll
            for (int nt = 0; nt < 8; nt++) {
                S[nt][0] = ex2(S[nt][0] - nmA);
                S[nt][1] = ex2(S[nt][1] - nmA);
                S[nt][2] = ex2(S[nt][2] - nmB);
                S[nt][3] = ex2(S[nt][3] - nmB);
                sA += S[nt][0] + S[nt][1];
                sB += S[nt][2] + S[nt][3];
            }
            #pragma unroll
            for (int o = 1; o <= 2; o <<= 1) {
                sA += __shfl_xor_sync(0xffffffffu, sA, o);
                sB += __shfl_xor_sync(0xffffffffu, sB, o);
            }
            float scA = ex2(mrow[0] - nmA), scB = ex2(mrow[1] - nmB);
            lrow[0] = lrow[0] * scA + sA;  mrow[0] = nmA;
            lrow[1] = lrow[1] * scB + sB;  mrow[1] = nmB;
            #pragma unroll
            for (int nt = 0; nt < 8; nt++) {
                O[nt][0] *= scA; O[nt][1] *= scA;
                O[nt][2] *= scB; O[nt][3] *= scB;
            }

            // O += P V : repack S C-frags to A-frags via shuffles, mma
            const int src0 = (lane & ~3) | (tg >> 1);
            const int src1 = src0 + 2;
            const bool odd = tg & 1;
            #pragma unroll
            for (int j = 0; j < 8; j++) {
                float v00 = __shfl_sync(0xffffffffu, S[j][0], src0);
                float v01 = __shfl_sync(0xffffffffu, S[j][1], src0);
                float v02 = __shfl_sync(0xffffffffu, S[j][2], src0);
                float v03 = __shfl_sync(0xffffffffu, S[j][3], src0);
                float v10 = __shfl_sync(0xffffffffu, S[j][0], src1);
                float v11 = __shfl_sync(0xffffffffu, S[j][1], src1);
                float v12 = __shfl_sync(0xffffffffu, S[j][2], src1);
                float v13 = __shfl_sync(0xffffffffu, S[j][3], src1);
                unsigned a[4];
                a[0] = rtf_u(odd ? v01 : v00);   // P(g,    8j+tg)
                a[1] = rtf_u(odd ? v03 : v02);   // P(g+8,  8j+tg)
                a[2] = rtf_u(odd ? v11 : v10);   // P(g,    8j+tg+4)
                a[3] = rtf_u(odd ? v13 : v12);   // P(g+8,  8j+tg+4)
                #pragma unroll
                for (int nt = 0; nt < 8; nt++) {
                    unsigned bv[2];
                    bv[0] = f2u(Vb[(j * 8 + tg    ) * 72 + nt * 8 + g]);
                    bv[1] = f2u(Vb[(j * 8 + tg + 4) * 72 + nt * 8 + g]);
                    mma8(O[nt], a, bv);
                }
            }
        }
    }

    // normalize + write ctx d-PERMUTED (A operand of the Wo gemm)
    float invA = 1.0f / lrow[0], invB = 1.0f / lrow[1];
    int tA = q0 + wq + g, tB = tA + 8;
    float* rowA = &ctx[((size_t)b * Tt + tA) * Dd];
    float* rowB = &ctx[((size_t)b * Tt + tB) * Dd];
    #pragma unroll
    for (int nt = 0; nt < 8; nt++) {
        int c = h * HDIM + nt * 8 + 2 * tg;
        int p0 = kpos(c), p1 = kpos(c + 1);
        rowA[p0] = rtf(O[nt][0] * invA);
        rowA[p1] = rtf(O[nt][1] * invA);
        rowB[p0] = rtf(O[nt][2] * invB);
        rowB[p1] = rtf(O[nt][3] * invB);
    }
}

// ---------------------------------------------------------------------------
extern "C" void kernel_launch(void* const* d_in, const int* in_sizes, int n_in,
                              void* d_out, int out_size)
{
    const float* x  = (const float*)d_in[0];
    const float* Wq = (const float*)d_in[1];
    const float* Wk = (const float*)d_in[2];
    const float* Wv = (const float*)d_in[3];
    const float* Wo = (const float*)d_in[4];
    const float* bo = (const float*)d_in[5];
    float* out = (float*)d_out;

    float *pq, *pk, *pv, *pctx, *pxr, *pwt;
    cudaGetSymbolAddress((void**)&pq,   g_q);
    cudaGetSymbolAddress((void**)&pk,   g_k);
    cudaGetSymbolAddress((void**)&pv,   g_v);
    cudaGetSymbolAddress((void**)&pctx, g_ctx);
    cudaGetSymbolAddress((void**)&pxr,  g_xr);
    cudaGetSymbolAddress((void**)&pwt,  g_wt);
    float* wt0 = pwt;
    float* wt1 = pwt + (size_t)Dd*Dd;
    float* wt2 = pwt + 2*(size_t)Dd*Dd;
    float* wt3 = pwt + 3*(size_t)Dd*Dd;

    cudaFuncSetAttribute(gemm_mma,  cudaFuncAttributeMaxDynamicSharedMemorySize, GSMEM);
    cudaFuncSetAttribute(flash_mma, cudaFuncAttributeMaxDynamicSharedMemorySize, FSMEM);

    preround_x<<<4096, 256>>>(x);
    transW<<<dim3(32, 32, 4), dim3(32, 8)>>>(Wq, Wk, Wv, Wo);

    gemm_mma<<<dim3(Dd/128, MTOT/128, 3), 256, GSMEM>>>(
        pxr, wt0, wt1, wt2, pq, pk, pv, nullptr, 1);

    flash_mma<<<dim3(Tt/128, Hh, Bb), 256, FSMEM>>>(pq, pk, pv, pctx);

    gemm_mma<<<dim3(Dd/128, MTOT/128, 1), 256, GSMEM>>>(
        pctx, wt3, nullptr, nullptr, out, nullptr, nullptr, bo, 0);
}